// round 6
// baseline (speedup 1.0000x reference)
#include <cuda_runtime.h>
#include <cuda_bf16.h>
#include <math.h>
#include <stdint.h>

#define HID   1024
#define OUTD  768
#define BATCH 256
#define TMAX  256
#define NJB   (HID / 32)

// ===========================================================================
// helpers
// ===========================================================================
__device__ __forceinline__ uint32_t smem_u32(const void* p) {
    uint32_t a;
    asm("{ .reg .u64 t; cvta.to.shared.u64 t, %1; cvt.u32.u64 %0, t; }" : "=r"(a) : "l"(p));
    return a;
}
__device__ __host__ __forceinline__ uint32_t sw128(uint32_t off) {
    return off ^ ((off >> 3) & 0x70);
}
__device__ __forceinline__ void cpa16(uint32_t dst, const void* src) {
    asm volatile("cp.async.cg.shared.global [%0], [%1], 16;" :: "r"(dst), "l"(src));
}
#define CP_COMMIT() asm volatile("cp.async.commit_group;" ::: "memory")
#define CP_WAIT(n)  asm volatile("cp.async.wait_group %0;" :: "n"(n) : "memory")

__device__ __forceinline__ void ldsm4(uint32_t (&r)[4], uint32_t addr) {
    asm volatile("ldmatrix.sync.aligned.m8n8.x4.shared.b16 {%0,%1,%2,%3}, [%4];"
        : "=r"(r[0]), "=r"(r[1]), "=r"(r[2]), "=r"(r[3]) : "r"(addr));
}
__device__ __forceinline__ void mma16816(float (&d)[4], const uint32_t (&a)[4],
                                         uint32_t b0, uint32_t b1) {
    asm volatile("mma.sync.aligned.m16n8k16.row.col.f32.bf16.bf16.f32 "
        "{%0,%1,%2,%3}, {%4,%5,%6,%7}, {%8,%9}, {%0,%1,%2,%3};"
        : "+f"(d[0]), "+f"(d[1]), "+f"(d[2]), "+f"(d[3])
        : "r"(a[0]), "r"(a[1]), "r"(a[2]), "r"(a[3]), "r"(b0), "r"(b1));
}

// ===========================================================================
// device scratch
// ===========================================================================
__device__ float g_H[(TMAX + 1) * BATCH * HID];
__device__ float g_Wih_f[NJB * OUTD * 3 * 32];
__device__ float g_Whh_f[NJB * HID * 3 * 32];
__device__ float g_Wc[3 * HID * HID];
__device__ float g_bcomb[3 * HID];
// pre-swizzled SW128 bf16 tile images
__device__ __align__(1024) char g_Aimg[(size_t)(TMAX + 1) * 2 * 16 * 32768]; // [t][mh][kc]{hi16K,lo16K}
__device__ __align__(1024) char g_Wimg[(size_t)64 * 16 * 24576];             // [nt][kc]{hi12K,lo12K}
__device__ __align__(1024) char g_Wfcimg[(size_t)6 * 16 * 32768];            // [nt][kc]{hi16K,lo16K}

// ===========================================================================
// fp32 SIMT pieces (step 0 + W_comb precompute) — proven in R1
// ===========================================================================
__device__ __forceinline__ unsigned long long dup2(float x) {
    unsigned long long r;
    asm("mov.b64 %0, {%1, %1};" : "=l"(r) : "f"(x));
    return r;
}
__device__ __forceinline__ void fmax2(unsigned long long& d, unsigned long long a,
                                      unsigned long long b) {
    asm("fma.rn.f32x2 %0, %1, %2, %0;" : "+l"(d) : "l"(a), "l"(b));
}
union F4U { float4 f; unsigned long long u[2]; };
union U2F { unsigned long long u; float2 f; };
__device__ __forceinline__ float sigmf(float x) { return 1.0f / (1.0f + __expf(-x)); }

__global__ __launch_bounds__(256) void pack_w(float* __restrict__ dst,
                                              const float* __restrict__ src, int Ks) {
    __shared__ float sm[32][33];
    int k0 = blockIdx.x * 32, jb = blockIdx.y, g = blockIdx.z, t = threadIdx.x;
    int jl = t >> 3, kq = t & 7;
    float4 v = *(const float4*)(src + (size_t)(g * HID + jb * 32 + jl) * Ks + k0 + kq * 4);
    sm[jl][kq * 4 + 0] = v.x; sm[jl][kq * 4 + 1] = v.y;
    sm[jl][kq * 4 + 2] = v.z; sm[jl][kq * 4 + 3] = v.w;
    __syncthreads();
    int ji = t & 31, kk0 = t >> 5;
#pragma unroll
    for (int r = 0; r < 4; r++) {
        int kk = kk0 + r * 8;
        dst[(((size_t)jb * Ks + k0 + kk) * 3 + g) * 32 + ji] = sm[ji][kk];
    }
}

__global__ __launch_bounds__(256) void bcomb_k(const float* __restrict__ Wih,
                                               const float* __restrict__ bfc,
                                               const float* __restrict__ bih,
                                               float* __restrict__ out) {
    int j = blockIdx.x * 8 + (threadIdx.x >> 5);
    int lane = threadIdx.x & 31;
    float s = 0.f;
    for (int o = lane; o < OUTD; o += 32) s += Wih[(size_t)j * OUTD + o] * bfc[o];
#pragma unroll
    for (int off = 16; off; off >>= 1) s += __shfl_xor_sync(0xffffffffu, s, off);
    if (lane == 0) out[j] = s + bih[j];
}

__global__ __launch_bounds__(256) void copy_f(float* __restrict__ dst,
                                              const float* __restrict__ src, int n4) {
    int i = blockIdx.x * 256 + threadIdx.x;
    if (i < n4) ((float4*)dst)[i] = ((const float4*)src)[i];
}

__global__ __launch_bounds__(256) void gemm_nn(const float* __restrict__ A,
                                               const float* __restrict__ B,
                                               const float* __restrict__ bias,
                                               float* __restrict__ C,
                                               int M, int N, int K) {
    __shared__ float2 sA[32][66];
    __shared__ float  sB[32][64];
    int n0 = blockIdx.x * 64, m0 = blockIdx.y * 128, t = threadIdx.x;
    int tn = t & 15, tm = t >> 4;
    unsigned long long acc[4][4] = {};
    float4 ast[4], bst[2];
#pragma unroll
    for (int r = 0; r < 4; r++) {
        int idx = t + 256 * r, m = idx >> 3, kf = idx & 7;
        ast[r] = *(const float4*)(A + (size_t)(m0 + m) * K + kf * 4);
    }
#pragma unroll
    for (int r = 0; r < 2; r++) {
        int idx = t + 256 * r, kk = idx >> 4, nf = idx & 15;
        bst[r] = *(const float4*)(B + (size_t)kk * N + n0 + nf * 4);
    }
    int nch = K >> 5;
    for (int ch = 0; ch < nch; ch++) {
        float* sp = (float*)&sA[0][0];
#pragma unroll
        for (int r = 0; r < 4; r++) {
            int idx = t + 256 * r, m = idx >> 3, kf = idx & 7;
            sp[(kf * 4 + 0) * 132 + m] = ast[r].x; sp[(kf * 4 + 1) * 132 + m] = ast[r].y;
            sp[(kf * 4 + 2) * 132 + m] = ast[r].z; sp[(kf * 4 + 3) * 132 + m] = ast[r].w;
        }
#pragma unroll
        for (int r = 0; r < 2; r++) {
            int idx = t + 256 * r, kk = idx >> 4, nf = idx & 15;
            *(float4*)&sB[kk][nf * 4] = bst[r];
        }
        __syncthreads();
        if (ch + 1 < nch) {
            int k0 = (ch + 1) * 32;
#pragma unroll
            for (int r = 0; r < 4; r++) {
                int idx = t + 256 * r, m = idx >> 3, kf = idx & 7;
                ast[r] = *(const float4*)(A + (size_t)(m0 + m) * K + k0 + kf * 4);
            }
#pragma unroll
            for (int r = 0; r < 2; r++) {
                int idx = t + 256 * r, kk = idx >> 4, nf = idx & 15;
                bst[r] = *(const float4*)(B + (size_t)(k0 + kk) * N + n0 + nf * 4);
            }
        }
#pragma unroll 8
        for (int k = 0; k < 32; k++) {
            F4U a0, a1, bv;
            a0.f = *(const float4*)&sA[k][tm * 4];
            a1.f = *(const float4*)&sA[k][tm * 4 + 2];
            bv.f = *(const float4*)&sB[k][tn * 4];
            unsigned long long d0 = dup2(bv.f.x), d1 = dup2(bv.f.y),
                               d2 = dup2(bv.f.z), d3 = dup2(bv.f.w);
            fmax2(acc[0][0], a0.u[0], d0); fmax2(acc[0][1], a0.u[1], d0);
            fmax2(acc[0][2], a1.u[0], d0); fmax2(acc[0][3], a1.u[1], d0);
            fmax2(acc[1][0], a0.u[0], d1); fmax2(acc[1][1], a0.u[1], d1);
            fmax2(acc[1][2], a1.u[0], d1); fmax2(acc[1][3], a1.u[1], d1);
            fmax2(acc[2][0], a0.u[0], d2); fmax2(acc[2][1], a0.u[1], d2);
            fmax2(acc[2][2], a1.u[0], d2); fmax2(acc[2][3], a1.u[1], d2);
            fmax2(acc[3][0], a0.u[0], d3); fmax2(acc[3][1], a0.u[1], d3);
            fmax2(acc[3][2], a1.u[0], d3); fmax2(acc[3][3], a1.u[1], d3);
        }
        __syncthreads();
    }
#pragma unroll
    for (int ni = 0; ni < 4; ni++) {
        int n = n0 + tn * 4 + ni;
        float bv = bias ? bias[n] : 0.f;
#pragma unroll
        for (int p = 0; p < 4; p++) {
            U2F v; v.u = acc[ni][p];
            int m = m0 + tm * 8 + p * 2;
            C[(size_t)m * N + n] = v.f.x + bv;
            C[(size_t)(m + 1) * N + n] = v.f.y + bv;
        }
    }
}

// SIMT GRU step (step 0 only, K=768 input path)
__device__ __forceinline__ void gru_phase(unsigned long long (&acc)[3][4],
                                          const float* __restrict__ src, int Kd,
                                          const float* __restrict__ Wf,
                                          int jb, int b0, int t, int tx, int ty,
                                          float* sW, float2 (*sH)[34]) {
    const float* Wp = Wf + (size_t)jb * Kd * 96;
    int nch = Kd >> 5;
    float4 wst0, wst1, wst2, hst0, hst1;
    {
        const float4* wp4 = (const float4*)Wp;
        wst0 = wp4[t]; wst1 = wp4[t + 256]; wst2 = wp4[t + 512];
        int i0 = t, i1 = t + 256;
        hst0 = *(const float4*)(src + (size_t)(b0 + (i0 >> 3)) * Kd + ((i0 & 7) << 2));
        hst1 = *(const float4*)(src + (size_t)(b0 + (i1 >> 3)) * Kd + ((i1 & 7) << 2));
    }
    for (int ch = 0; ch < nch; ch++) {
        ((float4*)sW)[t] = wst0; ((float4*)sW)[t + 256] = wst1; ((float4*)sW)[t + 512] = wst2;
        float* sp = (float*)&sH[0][0];
        {
            int m = t >> 3, kf = t & 7;
            sp[(kf * 4 + 0) * 68 + m] = hst0.x; sp[(kf * 4 + 1) * 68 + m] = hst0.y;
            sp[(kf * 4 + 2) * 68 + m] = hst0.z; sp[(kf * 4 + 3) * 68 + m] = hst0.w;
            int i1 = t + 256; m = i1 >> 3; kf = i1 & 7;
            sp[(kf * 4 + 0) * 68 + m] = hst1.x; sp[(kf * 4 + 1) * 68 + m] = hst1.y;
            sp[(kf * 4 + 2) * 68 + m] = hst1.z; sp[(kf * 4 + 3) * 68 + m] = hst1.w;
        }
        __syncthreads();
        if (ch + 1 < nch) {
            int k0 = (ch + 1) * 32;
            const float4* wp4 = (const float4*)(Wp + (size_t)k0 * 96);
            wst0 = wp4[t]; wst1 = wp4[t + 256]; wst2 = wp4[t + 512];
            int i0 = t, i1 = t + 256;
            hst0 = *(const float4*)(src + (size_t)(b0 + (i0 >> 3)) * Kd + k0 + ((i0 & 7) << 2));
            hst1 = *(const float4*)(src + (size_t)(b0 + (i1 >> 3)) * Kd + k0 + ((i1 & 7) << 2));
        }
#pragma unroll 8
        for (int k = 0; k < 32; k++) {
            F4U a0, a1;
            a0.f = *(const float4*)&sH[k][ty * 4];
            a1.f = *(const float4*)&sH[k][ty * 4 + 2];
            float w0 = sW[k * 96 + tx], w1 = sW[k * 96 + 32 + tx], w2 = sW[k * 96 + 64 + tx];
            unsigned long long d0 = dup2(w0), d1 = dup2(w1), d2 = dup2(w2);
            fmax2(acc[0][0], a0.u[0], d0); fmax2(acc[0][1], a0.u[1], d0);
            fmax2(acc[0][2], a1.u[0], d0); fmax2(acc[0][3], a1.u[1], d0);
            fmax2(acc[1][0], a0.u[0], d1); fmax2(acc[1][1], a0.u[1], d1);
            fmax2(acc[1][2], a1.u[0], d1); fmax2(acc[1][3], a1.u[1], d1);
            fmax2(acc[2][0], a0.u[0], d2); fmax2(acc[2][1], a0.u[1], d2);
            fmax2(acc[2][2], a1.u[0], d2); fmax2(acc[2][3], a1.u[1], d2);
        }
        __syncthreads();
    }
}

__global__ __launch_bounds__(256) void gru_step(const float* __restrict__ inp, int Ki,
                                                const float* __restrict__ Wi,
                                                const float* __restrict__ bi,
                                                const float* __restrict__ hin,
                                                const float* __restrict__ Wh,
                                                const float* __restrict__ bh,
                                                float* __restrict__ hout) {
    __shared__ float  sW[32 * 96];
    __shared__ float2 sH[32][34];
    int jb = blockIdx.x, b0 = blockIdx.y * 64, t = threadIdx.x;
    int tx = t & 31, ty = t >> 5;
    unsigned long long acci[3][4] = {};
    unsigned long long acch[3][4] = {};
    gru_phase(acci, inp, Ki, Wi, jb, b0, t, tx, ty, sW, sH);
    gru_phase(acch, hin, HID, Wh, jb, b0, t, tx, ty, sW, sH);
    int j = jb * 32 + tx;
    float bir = bi[j], bhr = bh[j];
    float biz = bi[HID + j], bhz = bh[HID + j];
    float bin_ = bi[2 * HID + j], bhn = bh[2 * HID + j];
#pragma unroll
    for (int p = 0; p < 4; p++) {
        U2F ir, iz, in_, hr, hz, hn;
        ir.u = acci[0][p]; iz.u = acci[1][p]; in_.u = acci[2][p];
        hr.u = acch[0][p]; hz.u = acch[1][p]; hn.u = acch[2][p];
        int b = b0 + ty * 8 + p * 2;
        float r0 = sigmf(ir.f.x + bir + hr.f.x + bhr);
        float z0 = sigmf(iz.f.x + biz + hz.f.x + bhz);
        float n0 = tanhf(in_.f.x + bin_ + r0 * (hn.f.x + bhn));
        float hp0 = hin[(size_t)b * HID + j];
        hout[(size_t)b * HID + j] = (1.f - z0) * n0 + z0 * hp0;
        float r1 = sigmf(ir.f.y + bir + hr.f.y + bhr);
        float z1 = sigmf(iz.f.y + biz + hz.f.y + bhz);
        float n1 = tanhf(in_.f.y + bin_ + r1 * (hn.f.y + bhn));
        float hp1 = hin[(size_t)(b + 1) * HID + j];
        hout[(size_t)(b + 1) * HID + j] = (1.f - z1) * n1 + z1 * hp1;
    }
}

// ===========================================================================
// bf16 hi/lo split + image packers
// ===========================================================================
union BPK { unsigned short s[8]; uint4 v; };
__device__ __forceinline__ void split8(const float* v, uint4& hi, uint4& lo) {
    BPK ph, pl;
#pragma unroll
    for (int i = 0; i < 8; i++) {
        __nv_bfloat16 a = __float2bfloat16(v[i]);
        float r = v[i] - __bfloat162float(a);
        __nv_bfloat16 b = __float2bfloat16(r);
        ph.s[i] = *(unsigned short*)&a;
        pl.s[i] = *(unsigned short*)&b;
    }
    hi = ph.v; lo = pl.v;
}

// W_cat images: nt(64) x kc(16): 96 rows x 64 k-cols, rows interleave i/h x gates
__global__ __launch_bounds__(256) void pack_wimg(const float* __restrict__ Wc,
                                                 const float* __restrict__ Whh) {
    int nt = blockIdx.x, kc = blockIdx.y, tid = threadIdx.x;
    char* dst = g_Wimg + ((size_t)nt * 16 + kc) * 24576;
    for (int u = tid; u < 768; u += 256) {
        int r = u >> 3, unit = u & 7;
        int jt = r / 6, c = r % 6;
        int part = c & 1, g = c >> 1;
        int j = nt * 16 + jt;
        const float* srcrow = (part ? Whh : Wc) + (size_t)(g * HID + j) * HID + kc * 64 + unit * 8;
        float v[8];
        *(float4*)&v[0] = *(const float4*)srcrow;
        *(float4*)&v[4] = *(const float4*)(srcrow + 4);
        uint4 hi, lo; split8(v, hi, lo);
        uint32_t o = sw128((uint32_t)(r * 128 + unit * 16));
        *(uint4*)(dst + o) = hi;
        *(uint4*)(dst + 12288 + o) = lo;
    }
}

// W_fc images: nt(6) x kc(16): 128 rows x 64 k-cols
__global__ __launch_bounds__(256) void pack_wfcimg(const float* __restrict__ Wfc) {
    int nt = blockIdx.x, kc = blockIdx.y, tid = threadIdx.x;
    char* dst = g_Wfcimg + ((size_t)nt * 16 + kc) * 32768;
    for (int u = tid; u < 1024; u += 256) {
        int r = u >> 3, unit = u & 7;
        const float* srcrow = Wfc + (size_t)(nt * 128 + r) * HID + kc * 64 + unit * 8;
        float v[8];
        *(float4*)&v[0] = *(const float4*)srcrow;
        *(float4*)&v[4] = *(const float4*)(srcrow + 4);
        uint4 hi, lo; split8(v, hi, lo);
        uint32_t o = sw128((uint32_t)(r * 128 + unit * 16));
        *(uint4*)(dst + o) = hi;
        *(uint4*)(dst + 16384 + o) = lo;
    }
}

// h_1 (SIMT step 0 result) -> A image for t=1
__global__ __launch_bounds__(256) void h2img() {
    int mh = blockIdx.x, kc = blockIdx.y, tid = threadIdx.x;
    char* dst = g_Aimg + ((size_t)(1 * 2 + mh) * 16 + kc) * 32768;
    for (int u = tid; u < 1024; u += 256) {
        int r = u >> 3, unit = u & 7;
        const float* hp = g_H + ((size_t)1 * BATCH + mh * 128 + r) * HID + kc * 64 + unit * 8;
        float v[8];
        *(float4*)&v[0] = *(const float4*)hp;
        *(float4*)&v[4] = *(const float4*)(hp + 4);
        uint4 hi, lo; split8(v, hi, lo);
        uint32_t o = sw128((uint32_t)(r * 128 + unit * 16));
        *(uint4*)(dst + o) = hi;
        *(uint4*)(dst + 16384 + o) = lo;
    }
}

// ===========================================================================
// HMMA GRU step: D[128 x 96] = h @ Wcat^T (bf16 hi/lo x3), gates in epilogue
// grid (64 nt, 2 mh), 256 threads (8 warps, 4m x 2n, warp tile 32x48)
// ===========================================================================
#define STG 57344
#define STEP_DYN (2 * STG)

__global__ __launch_bounds__(256, 1) void gru_step_mma(int t, const float* __restrict__ bhh) {
    extern __shared__ char dsm[];
    uint32_t base = smem_u32(dsm);
    int tid = threadIdx.x;
    int wid = tid >> 5, lane = tid & 31;
    int nt = blockIdx.x, mh = blockIdx.y;
    int wm = wid & 3, wn = wid >> 2;

    const char* Asrc = g_Aimg + (size_t)(t * 2 + mh) * (16 * 32768);
    const char* Bsrc = g_Wimg + (size_t)nt * (16 * 24576);

    float acc[2][6][4];
#pragma unroll
    for (int a = 0; a < 2; a++)
#pragma unroll
        for (int b = 0; b < 6; b++)
#pragma unroll
            for (int c = 0; c < 4; c++) acc[a][b][c] = 0.f;

    // prologue: chunk 0 -> stage 0
    {
        uint32_t d = base;
        const char* ap = Asrc;
        const char* bp = Bsrc;
#pragma unroll
        for (int q = 0; q < 8; q++) cpa16(d + q * 4096 + tid * 16, ap + q * 4096 + tid * 16);
#pragma unroll
        for (int q = 0; q < 6; q++) cpa16(d + 32768 + q * 4096 + tid * 16, bp + q * 4096 + tid * 16);
        CP_COMMIT();
    }

    for (int c = 0; c < 16; c++) {
        if (c < 15) {
            uint32_t d = base + ((c + 1) & 1) * STG;
            const char* ap = Asrc + (size_t)(c + 1) * 32768;
            const char* bp = Bsrc + (size_t)(c + 1) * 24576;
#pragma unroll
            for (int q = 0; q < 8; q++) cpa16(d + q * 4096 + tid * 16, ap + q * 4096 + tid * 16);
#pragma unroll
            for (int q = 0; q < 6; q++) cpa16(d + 32768 + q * 4096 + tid * 16, bp + q * 4096 + tid * 16);
            CP_COMMIT();
            CP_WAIT(1);
        } else {
            CP_WAIT(0);
        }
        __syncthreads();
        uint32_t sA = base + (c & 1) * STG;
        uint32_t sB = sA + 32768;
#pragma unroll
        for (int kk = 0; kk < 4; kk++) {
            uint32_t ah[2][4], al[2][4], bh[3][4], bl[3][4];
            int seg = kk * 32 + (lane >> 4) * 16;
#pragma unroll
            for (int mt = 0; mt < 2; mt++) {
                int r = wm * 32 + mt * 16 + (lane & 15);
                uint32_t off = sw128((uint32_t)(r * 128 + seg));
                ldsm4(ah[mt], sA + off);
                ldsm4(al[mt], sA + 16384 + off);
            }
#pragma unroll
            for (int nq = 0; nq < 3; nq++) {
                int r = wn * 48 + nq * 16 + (lane & 15);
                uint32_t off = sw128((uint32_t)(r * 128 + seg));
                ldsm4(bh[nq], sB + off);
                ldsm4(bl[nq], sB + 12288 + off);
            }
#pragma unroll
            for (int mt = 0; mt < 2; mt++)
#pragma unroll
                for (int n8 = 0; n8 < 6; n8++) {
                    int nq = n8 >> 1, hf = n8 & 1;
                    mma16816(acc[mt][n8], ah[mt], bh[nq][hf], bh[nq][hf + 2]);
                    mma16816(acc[mt][n8], ah[mt], bl[nq][hf], bl[nq][hf + 2]);
                    mma16816(acc[mt][n8], al[mt], bh[nq][hf], bh[nq][hf + 2]);
                }
        }
        __syncthreads();
    }

    // epilogue: accs -> smem [128][96] (stride 100), then gates
    float* sf = (float*)dsm;
    int m0 = wm * 32, n0 = wn * 48;
#pragma unroll
    for (int mt = 0; mt < 2; mt++)
#pragma unroll
        for (int n8 = 0; n8 < 6; n8++) {
            int r0 = m0 + mt * 16 + (lane >> 2);
            int c0 = n0 + n8 * 8 + 2 * (lane & 3);
            *(float2*)&sf[r0 * 100 + c0]       = make_float2(acc[mt][n8][0], acc[mt][n8][1]);
            *(float2*)&sf[(r0 + 8) * 100 + c0] = make_float2(acc[mt][n8][2], acc[mt][n8][3]);
        }
    __syncthreads();

    int r = tid >> 1, uh = tid & 1;
    int b = mh * 128 + r;
    int j0 = nt * 16 + uh * 8;
    const float* hprev = g_H + ((size_t)t * BATCH + b) * HID + j0;
    float* hnew = g_H + ((size_t)(t + 1) * BATCH + b) * HID + j0;
    float hp[8], hv[8];
    *(float4*)&hp[0] = *(const float4*)(hprev);
    *(float4*)&hp[4] = *(const float4*)(hprev + 4);
#pragma unroll
    for (int i = 0; i < 8; i++) {
        const float* g6 = &sf[r * 100 + (uh * 8 + i) * 6];
        int j = j0 + i;
        float rg = sigmf(g6[0] + g_bcomb[j] + g6[1] + bhh[j]);
        float zg = sigmf(g6[2] + g_bcomb[HID + j] + g6[3] + bhh[HID + j]);
        float ng = tanhf(g6[4] + g_bcomb[2 * HID + j] + rg * (g6[5] + bhh[2 * HID + j]));
        hv[i] = (1.f - zg) * ng + zg * hp[i];
    }
    *(float4*)(hnew)     = *(float4*)&hv[0];
    *(float4*)(hnew + 4) = *(float4*)&hv[4];

    uint4 hi, lo;
    split8(hv, hi, lo);
    char* dst = g_Aimg + ((size_t)((t + 1) * 2 + mh) * 16 + (nt >> 2)) * 32768;
    uint32_t o = sw128((uint32_t)(r * 128 + (nt & 3) * 32 + uh * 16));
    *(uint4*)(dst + o) = hi;
    *(uint4*)(dst + 16384 + o) = lo;
}

// ===========================================================================
// HMMA output GEMM: Y[(t-1)*256+b][o] = h_t @ Wfc^T + bfc
// grid (6 nt, 2 mh, T), 256 threads (8 warps, 4m x 2n, warp tile 32x64)
// ===========================================================================
#define OSTG 65536
#define OUT_DYN (2 * OSTG)

__global__ __launch_bounds__(256, 1) void out_gemm_mma(float* __restrict__ out,
                                                       const float* __restrict__ bfc) {
    extern __shared__ char dsm[];
    uint32_t base = smem_u32(dsm);
    int tid = threadIdx.x;
    int wid = tid >> 5, lane = tid & 31;
    int nt = blockIdx.x, mh = blockIdx.y;
    int t = blockIdx.z + 1;
    int wm = wid & 3, wn = wid >> 2;

    const char* Asrc = g_Aimg + (size_t)(t * 2 + mh) * (16 * 32768);
    const char* Bsrc = g_Wfcimg + (size_t)nt * (16 * 32768);

    float acc[2][8][4];
#pragma unroll
    for (int a = 0; a < 2; a++)
#pragma unroll
        for (int b = 0; b < 8; b++)
#pragma unroll
            for (int c = 0; c < 4; c++) acc[a][b][c] = 0.f;

    {
        uint32_t d = base;
#pragma unroll
        for (int q = 0; q < 8; q++) cpa16(d + q * 4096 + tid * 16, Asrc + q * 4096 + tid * 16);
#pragma unroll
        for (int q = 0; q < 8; q++) cpa16(d + 32768 + q * 4096 + tid * 16, Bsrc + q * 4096 + tid * 16);
        CP_COMMIT();
    }

    for (int c = 0; c < 16; c++) {
        if (c < 15) {
            uint32_t d = base + ((c + 1) & 1) * OSTG;
            const char* ap = Asrc + (size_t)(c + 1) * 32768;
            const char* bp = Bsrc + (size_t)(c + 1) * 32768;
#pragma unroll
            for (int q = 0; q < 8; q++) cpa16(d + q * 4096 + tid * 16, ap + q * 4096 + tid * 16);
#pragma unroll
            for (int q = 0; q < 8; q++) cpa16(d + 32768 + q * 4096 + tid * 16, bp + q * 4096 + tid * 16);
            CP_COMMIT();
            CP_WAIT(1);
        } else {
            CP_WAIT(0);
        }
        __syncthreads();
        uint32_t sA = base + (c & 1) * OSTG;
        uint32_t sB = sA + 32768;
#pragma unroll
        for (int kk = 0; kk < 4; kk++) {
            uint32_t ah[2][4], al[2][4], bh[4][4], bl[4][4];
            int seg = kk * 32 + (lane >> 4) * 16;
#pragma unroll
            for (int mt = 0; mt < 2; mt++) {
                int r = wm * 32 + mt * 16 + (lane & 15);
                uint32_t off = sw128((uint32_t)(r * 128 + seg));
                ldsm4(ah[mt], sA + off);
                ldsm4(al[mt], sA + 16384 + off);
            }
#pragma unroll
            for (int nq = 0; nq < 4; nq++) {
                int r = wn * 64 + nq * 16 + (lane & 15);
                uint32_t off = sw128((uint32_t)(r * 128 + seg));
                ldsm4(bh[nq], sB + off);
                ldsm4(bl[nq], sB + 16384 + off);
            }
#pragma unroll
            for (int mt = 0; mt < 2; mt++)
#pragma unroll
                for (int n8 = 0; n8 < 8; n8++) {
                    int nq = n8 >> 1, hf = n8 & 1;
                    mma16816(acc[mt][n8], ah[mt], bh[nq][hf], bh[nq][hf + 2]);
                    mma16816(acc[mt][n8], ah[mt], bl[nq][hf], bl[nq][hf + 2]);
                    mma16816(acc[mt][n8], al[mt], bh[nq][hf], bh[nq][hf + 2]);
                }
        }
        __syncthreads();
    }

    // direct global epilogue with bias
    size_t row0 = (size_t)(t - 1) * BATCH + mh * 128;
#pragma unroll
    for (int mt = 0; mt < 2; mt++)
#pragma unroll
        for (int n8 = 0; n8 < 8; n8++) {
            int rr = wm * 32 + mt * 16 + (lane >> 2);
            int cc = nt * 128 + wn * 64 + n8 * 8 + 2 * (lane & 3);
            float2 bv = *(const float2*)(bfc + cc);
            float2 v0 = make_float2(acc[mt][n8][0] + bv.x, acc[mt][n8][1] + bv.y);
            float2 v1 = make_float2(acc[mt][n8][2] + bv.x, acc[mt][n8][3] + bv.y);
            *(float2*)(out + (row0 + rr) * OUTD + cc)     = v0;
            *(float2*)(out + (row0 + rr + 8) * OUTD + cc) = v1;
        }
}

// ===========================================================================
extern "C" void kernel_launch(void* const* d_in, const int* in_sizes, int n_in,
                              void* d_out, int out_size) {
    const float* src    = (const float*)d_in[0];
    const float* hidden = (const float*)d_in[2];
    const float* W_ih   = (const float*)d_in[3];
    const float* W_hh   = (const float*)d_in[4];
    const float* b_ih   = (const float*)d_in[5];
    const float* b_hh   = (const float*)d_in[6];
    const float* W_fc   = (const float*)d_in[7];
    const float* b_fc   = (const float*)d_in[8];
    float* out = (float*)d_out;

    int T = out_size / (BATCH * OUTD);
    if (T > TMAX) T = TMAX;
    if (T < 1) T = 1;

    float *pH, *pWihf, *pWhhf, *pWc, *pbc;
    cudaGetSymbolAddress((void**)&pH, g_H);
    cudaGetSymbolAddress((void**)&pWihf, g_Wih_f);
    cudaGetSymbolAddress((void**)&pWhhf, g_Whh_f);
    cudaGetSymbolAddress((void**)&pWc, g_Wc);
    cudaGetSymbolAddress((void**)&pbc, g_bcomb);

    cudaFuncSetAttribute(gru_step_mma, cudaFuncAttributeMaxDynamicSharedMemorySize, STEP_DYN);
    cudaFuncSetAttribute(out_gemm_mma, cudaFuncAttributeMaxDynamicSharedMemorySize, OUT_DYN);

    // --- precompute ---
    pack_w<<<dim3(OUTD / 32, NJB, 3), 256>>>(pWihf, W_ih, OUTD);
    pack_w<<<dim3(HID / 32, NJB, 3), 256>>>(pWhhf, W_hh, HID);
    gemm_nn<<<dim3(HID / 64, (3 * HID) / 128), 256>>>(W_ih, W_fc, nullptr, pWc,
                                                      3 * HID, HID, OUTD);
    bcomb_k<<<(3 * HID) / 8, 256>>>(W_ih, b_fc, b_ih, pbc);
    copy_f<<<(BATCH * HID / 4 + 255) / 256, 256>>>(pH, hidden, BATCH * HID / 4);
    pack_wimg<<<dim3(64, 16), 256>>>(pWc, W_hh);
    pack_wfcimg<<<dim3(6, 16), 256>>>(W_fc);

    // --- step 0 (SIMT, K=768 input path) ---
    gru_step<<<dim3(NJB, BATCH / 64), 256>>>(src, OUTD, pWihf, b_ih,
                                             pH, pWhhf, b_hh,
                                             pH + (size_t)BATCH * HID);
    h2img<<<dim3(2, 16), 256>>>();

    // --- HMMA recurrence ---
    for (int ts = 1; ts < T; ts++)
        gru_step_mma<<<dim3(64, 2), 256, STEP_DYN>>>(ts, b_hh);

    // --- HMMA output projection ---
    out_gemm_mma<<<dim3(6, 2, T), 256, OUT_DYN>>>(out, b_fc);
}

// round 7
// speedup vs baseline: 1.2846x; 1.2846x over previous
#include <cuda_runtime.h>
#include <cuda_bf16.h>
#include <math.h>
#include <stdint.h>

#define HID   1024
#define OUTD  768
#define BATCH 256
#define TMAX  256
#define NJB   (HID / 32)

// ===========================================================================
// helpers
// ===========================================================================
__device__ __forceinline__ uint32_t smem_u32(const void* p) {
    uint32_t a;
    asm("{ .reg .u64 t; cvta.to.shared.u64 t, %1; cvt.u32.u64 %0, t; }" : "=r"(a) : "l"(p));
    return a;
}
__device__ __host__ __forceinline__ uint32_t sw128(uint32_t off) {
    return off ^ ((off >> 3) & 0x70);
}
__device__ __forceinline__ void cpa16(uint32_t dst, const void* src) {
    asm volatile("cp.async.cg.shared.global [%0], [%1], 16;" :: "r"(dst), "l"(src));
}
#define CP_COMMIT() asm volatile("cp.async.commit_group;" ::: "memory")
#define CP_WAIT(n)  asm volatile("cp.async.wait_group %0;" :: "n"(n) : "memory")

__device__ __forceinline__ void ldsm4(uint32_t (&r)[4], uint32_t addr) {
    asm volatile("ldmatrix.sync.aligned.m8n8.x4.shared.b16 {%0,%1,%2,%3}, [%4];"
        : "=r"(r[0]), "=r"(r[1]), "=r"(r[2]), "=r"(r[3]) : "r"(addr));
}
__device__ __forceinline__ void mma16816(float (&d)[4], const uint32_t (&a)[4],
                                         uint32_t b0, uint32_t b1) {
    asm volatile("mma.sync.aligned.m16n8k16.row.col.f32.bf16.bf16.f32 "
        "{%0,%1,%2,%3}, {%4,%5,%6,%7}, {%8,%9}, {%0,%1,%2,%3};"
        : "+f"(d[0]), "+f"(d[1]), "+f"(d[2]), "+f"(d[3])
        : "r"(a[0]), "r"(a[1]), "r"(a[2]), "r"(a[3]), "r"(b0), "r"(b1));
}

// ===========================================================================
// device scratch
// ===========================================================================
__device__ float g_H[(TMAX + 1) * BATCH * HID];
__device__ float g_Wih_f[NJB * OUTD * 3 * 32];
__device__ float g_Whh_f[NJB * HID * 3 * 32];
__device__ float g_Wc[3 * HID * HID];
__device__ float g_bcomb[3 * HID];
__device__ volatile unsigned g_bar;
// pre-swizzled SW128 bf16 tile images
__device__ __align__(1024) char g_Aimg[(size_t)(TMAX + 1) * 2 * 16 * 32768]; // [t][mh][kc]{hi16K,lo16K}
__device__ __align__(1024) char g_Wimg[(size_t)64 * 16 * 16384];             // fused [nt][kc]{hi8K,lo8K}
__device__ __align__(1024) char g_Wfcimg[(size_t)6 * 16 * 32768];            // [nt][kc]{hi16K,lo16K}

// ===========================================================================
// fp32 SIMT pieces (step 0 + W_comb precompute)
// ===========================================================================
__device__ __forceinline__ unsigned long long dup2(float x) {
    unsigned long long r;
    asm("mov.b64 %0, {%1, %1};" : "=l"(r) : "f"(x));
    return r;
}
__device__ __forceinline__ void fmax2(unsigned long long& d, unsigned long long a,
                                      unsigned long long b) {
    asm("fma.rn.f32x2 %0, %1, %2, %0;" : "+l"(d) : "l"(a), "l"(b));
}
union F4U { float4 f; unsigned long long u[2]; };
union U2F { unsigned long long u; float2 f; };
__device__ __forceinline__ float sigmf(float x) { return 1.0f / (1.0f + __expf(-x)); }

__global__ __launch_bounds__(256) void pack_w(float* __restrict__ dst,
                                              const float* __restrict__ src, int Ks) {
    __shared__ float sm[32][33];
    int k0 = blockIdx.x * 32, jb = blockIdx.y, g = blockIdx.z, t = threadIdx.x;
    int jl = t >> 3, kq = t & 7;
    float4 v = *(const float4*)(src + (size_t)(g * HID + jb * 32 + jl) * Ks + k0 + kq * 4);
    sm[jl][kq * 4 + 0] = v.x; sm[jl][kq * 4 + 1] = v.y;
    sm[jl][kq * 4 + 2] = v.z; sm[jl][kq * 4 + 3] = v.w;
    __syncthreads();
    int ji = t & 31, kk0 = t >> 5;
#pragma unroll
    for (int r = 0; r < 4; r++) {
        int kk = kk0 + r * 8;
        dst[(((size_t)jb * Ks + k0 + kk) * 3 + g) * 32 + ji] = sm[ji][kk];
    }
}

__global__ __launch_bounds__(256) void bcomb_k(const float* __restrict__ Wih,
                                               const float* __restrict__ bfc,
                                               const float* __restrict__ bih,
                                               float* __restrict__ out) {
    int j = blockIdx.x * 8 + (threadIdx.x >> 5);
    int lane = threadIdx.x & 31;
    float s = 0.f;
    for (int o = lane; o < OUTD; o += 32) s += Wih[(size_t)j * OUTD + o] * bfc[o];
#pragma unroll
    for (int off = 16; off; off >>= 1) s += __shfl_xor_sync(0xffffffffu, s, off);
    if (lane == 0) out[j] = s + bih[j];
}

__global__ __launch_bounds__(256) void copy_f(float* __restrict__ dst,
                                              const float* __restrict__ src, int n4) {
    int i = blockIdx.x * 256 + threadIdx.x;
    if (i < n4) ((float4*)dst)[i] = ((const float4*)src)[i];
}

__global__ void zero_bar() { g_bar = 0; }

__global__ __launch_bounds__(256) void gemm_nn(const float* __restrict__ A,
                                               const float* __restrict__ B,
                                               const float* __restrict__ bias,
                                               float* __restrict__ C,
                                               int M, int N, int K) {
    __shared__ float2 sA[32][66];
    __shared__ float  sB[32][64];
    int n0 = blockIdx.x * 64, m0 = blockIdx.y * 128, t = threadIdx.x;
    int tn = t & 15, tm = t >> 4;
    unsigned long long acc[4][4] = {};
    float4 ast[4], bst[2];
#pragma unroll
    for (int r = 0; r < 4; r++) {
        int idx = t + 256 * r, m = idx >> 3, kf = idx & 7;
        ast[r] = *(const float4*)(A + (size_t)(m0 + m) * K + kf * 4);
    }
#pragma unroll
    for (int r = 0; r < 2; r++) {
        int idx = t + 256 * r, kk = idx >> 4, nf = idx & 15;
        bst[r] = *(const float4*)(B + (size_t)kk * N + n0 + nf * 4);
    }
    int nch = K >> 5;
    for (int ch = 0; ch < nch; ch++) {
        float* sp = (float*)&sA[0][0];
#pragma unroll
        for (int r = 0; r < 4; r++) {
            int idx = t + 256 * r, m = idx >> 3, kf = idx & 7;
            sp[(kf * 4 + 0) * 132 + m] = ast[r].x; sp[(kf * 4 + 1) * 132 + m] = ast[r].y;
            sp[(kf * 4 + 2) * 132 + m] = ast[r].z; sp[(kf * 4 + 3) * 132 + m] = ast[r].w;
        }
#pragma unroll
        for (int r = 0; r < 2; r++) {
            int idx = t + 256 * r, kk = idx >> 4, nf = idx & 15;
            *(float4*)&sB[kk][nf * 4] = bst[r];
        }
        __syncthreads();
        if (ch + 1 < nch) {
            int k0 = (ch + 1) * 32;
#pragma unroll
            for (int r = 0; r < 4; r++) {
                int idx = t + 256 * r, m = idx >> 3, kf = idx & 7;
                ast[r] = *(const float4*)(A + (size_t)(m0 + m) * K + k0 + kf * 4);
            }
#pragma unroll
            for (int r = 0; r < 2; r++) {
                int idx = t + 256 * r, kk = idx >> 4, nf = idx & 15;
                bst[r] = *(const float4*)(B + (size_t)(k0 + kk) * N + n0 + nf * 4);
            }
        }
#pragma unroll 8
        for (int k = 0; k < 32; k++) {
            F4U a0, a1, bv;
            a0.f = *(const float4*)&sA[k][tm * 4];
            a1.f = *(const float4*)&sA[k][tm * 4 + 2];
            bv.f = *(const float4*)&sB[k][tn * 4];
            unsigned long long d0 = dup2(bv.f.x), d1 = dup2(bv.f.y),
                               d2 = dup2(bv.f.z), d3 = dup2(bv.f.w);
            fmax2(acc[0][0], a0.u[0], d0); fmax2(acc[0][1], a0.u[1], d0);
            fmax2(acc[0][2], a1.u[0], d0); fmax2(acc[0][3], a1.u[1], d0);
            fmax2(acc[1][0], a0.u[0], d1); fmax2(acc[1][1], a0.u[1], d1);
            fmax2(acc[1][2], a1.u[0], d1); fmax2(acc[1][3], a1.u[1], d1);
            fmax2(acc[2][0], a0.u[0], d2); fmax2(acc[2][1], a0.u[1], d2);
            fmax2(acc[2][2], a1.u[0], d2); fmax2(acc[2][3], a1.u[1], d2);
            fmax2(acc[3][0], a0.u[0], d3); fmax2(acc[3][1], a0.u[1], d3);
            fmax2(acc[3][2], a1.u[0], d3); fmax2(acc[3][3], a1.u[1], d3);
        }
        __syncthreads();
    }
#pragma unroll
    for (int ni = 0; ni < 4; ni++) {
        int n = n0 + tn * 4 + ni;
        float bv = bias ? bias[n] : 0.f;
#pragma unroll
        for (int p = 0; p < 4; p++) {
            U2F v; v.u = acc[ni][p];
            int m = m0 + tm * 8 + p * 2;
            C[(size_t)m * N + n] = v.f.x + bv;
            C[(size_t)(m + 1) * N + n] = v.f.y + bv;
        }
    }
}

// SIMT GRU step (step 0 only, K=768 input path)
__device__ __forceinline__ void gru_phase(unsigned long long (&acc)[3][4],
                                          const float* __restrict__ src, int Kd,
                                          const float* __restrict__ Wf,
                                          int jb, int b0, int t, int tx, int ty,
                                          float* sW, float2 (*sH)[34]) {
    const float* Wp = Wf + (size_t)jb * Kd * 96;
    int nch = Kd >> 5;
    float4 wst0, wst1, wst2, hst0, hst1;
    {
        const float4* wp4 = (const float4*)Wp;
        wst0 = wp4[t]; wst1 = wp4[t + 256]; wst2 = wp4[t + 512];
        int i0 = t, i1 = t + 256;
        hst0 = *(const float4*)(src + (size_t)(b0 + (i0 >> 3)) * Kd + ((i0 & 7) << 2));
        hst1 = *(const float4*)(src + (size_t)(b0 + (i1 >> 3)) * Kd + ((i1 & 7) << 2));
    }
    for (int ch = 0; ch < nch; ch++) {
        ((float4*)sW)[t] = wst0; ((float4*)sW)[t + 256] = wst1; ((float4*)sW)[t + 512] = wst2;
        float* sp = (float*)&sH[0][0];
        {
            int m = t >> 3, kf = t & 7;
            sp[(kf * 4 + 0) * 68 + m] = hst0.x; sp[(kf * 4 + 1) * 68 + m] = hst0.y;
            sp[(kf * 4 + 2) * 68 + m] = hst0.z; sp[(kf * 4 + 3) * 68 + m] = hst0.w;
            int i1 = t + 256; m = i1 >> 3; kf = i1 & 7;
            sp[(kf * 4 + 0) * 68 + m] = hst1.x; sp[(kf * 4 + 1) * 68 + m] = hst1.y;
            sp[(kf * 4 + 2) * 68 + m] = hst1.z; sp[(kf * 4 + 3) * 68 + m] = hst1.w;
        }
        __syncthreads();
        if (ch + 1 < nch) {
            int k0 = (ch + 1) * 32;
            const float4* wp4 = (const float4*)(Wp + (size_t)k0 * 96);
            wst0 = wp4[t]; wst1 = wp4[t + 256]; wst2 = wp4[t + 512];
            int i0 = t, i1 = t + 256;
            hst0 = *(const float4*)(src + (size_t)(b0 + (i0 >> 3)) * Kd + k0 + ((i0 & 7) << 2));
            hst1 = *(const float4*)(src + (size_t)(b0 + (i1 >> 3)) * Kd + k0 + ((i1 & 7) << 2));
        }
#pragma unroll 8
        for (int k = 0; k < 32; k++) {
            F4U a0, a1;
            a0.f = *(const float4*)&sH[k][ty * 4];
            a1.f = *(const float4*)&sH[k][ty * 4 + 2];
            float w0 = sW[k * 96 + tx], w1 = sW[k * 96 + 32 + tx], w2 = sW[k * 96 + 64 + tx];
            unsigned long long d0 = dup2(w0), d1 = dup2(w1), d2 = dup2(w2);
            fmax2(acc[0][0], a0.u[0], d0); fmax2(acc[0][1], a0.u[1], d0);
            fmax2(acc[0][2], a1.u[0], d0); fmax2(acc[0][3], a1.u[1], d0);
            fmax2(acc[1][0], a0.u[0], d1); fmax2(acc[1][1], a0.u[1], d1);
            fmax2(acc[1][2], a1.u[0], d1); fmax2(acc[1][3], a1.u[1], d1);
            fmax2(acc[2][0], a0.u[0], d2); fmax2(acc[2][1], a0.u[1], d2);
            fmax2(acc[2][2], a1.u[0], d2); fmax2(acc[2][3], a1.u[1], d2);
        }
        __syncthreads();
    }
}

__global__ __launch_bounds__(256) void gru_step(const float* __restrict__ inp, int Ki,
                                                const float* __restrict__ Wi,
                                                const float* __restrict__ bi,
                                                const float* __restrict__ hin,
                                                const float* __restrict__ Wh,
                                                const float* __restrict__ bh,
                                                float* __restrict__ hout) {
    __shared__ float  sW[32 * 96];
    __shared__ float2 sH[32][34];
    int jb = blockIdx.x, b0 = blockIdx.y * 64, t = threadIdx.x;
    int tx = t & 31, ty = t >> 5;
    unsigned long long acci[3][4] = {};
    unsigned long long acch[3][4] = {};
    gru_phase(acci, inp, Ki, Wi, jb, b0, t, tx, ty, sW, sH);
    gru_phase(acch, hin, HID, Wh, jb, b0, t, tx, ty, sW, sH);
    int j = jb * 32 + tx;
    float bir = bi[j], bhr = bh[j];
    float biz = bi[HID + j], bhz = bh[HID + j];
    float bin_ = bi[2 * HID + j], bhn = bh[2 * HID + j];
#pragma unroll
    for (int p = 0; p < 4; p++) {
        U2F ir, iz, in_, hr, hz, hn;
        ir.u = acci[0][p]; iz.u = acci[1][p]; in_.u = acci[2][p];
        hr.u = acch[0][p]; hz.u = acch[1][p]; hn.u = acch[2][p];
        int b = b0 + ty * 8 + p * 2;
        float r0 = sigmf(ir.f.x + bir + hr.f.x + bhr);
        float z0 = sigmf(iz.f.x + biz + hz.f.x + bhz);
        float n0 = tanhf(in_.f.x + bin_ + r0 * (hn.f.x + bhn));
        float hp0 = hin[(size_t)b * HID + j];
        hout[(size_t)b * HID + j] = (1.f - z0) * n0 + z0 * hp0;
        float r1 = sigmf(ir.f.y + bir + hr.f.y + bhr);
        float z1 = sigmf(iz.f.y + biz + hz.f.y + bhz);
        float n1 = tanhf(in_.f.y + bin_ + r1 * (hn.f.y + bhn));
        float hp1 = hin[(size_t)(b + 1) * HID + j];
        hout[(size_t)(b + 1) * HID + j] = (1.f - z1) * n1 + z1 * hp1;
    }
}

// ===========================================================================
// bf16 hi/lo split + image packers
// ===========================================================================
union BPK { unsigned short s[8]; uint4 v; };
__device__ __forceinline__ void split8(const float* v, uint4& hi, uint4& lo) {
    BPK ph, pl;
#pragma unroll
    for (int i = 0; i < 8; i++) {
        __nv_bfloat16 a = __float2bfloat16(v[i]);
        float r = v[i] - __bfloat162float(a);
        __nv_bfloat16 b = __float2bfloat16(r);
        ph.s[i] = *(unsigned short*)&a;
        pl.s[i] = *(unsigned short*)&b;
    }
    hi = ph.v; lo = pl.v;
}

// Gate-fused W images: nt(64) x kc(16): 64 rows x 64 k-cols.
// row = jt*4 + c;  c=0: Wc_r+Whh_r (summed), c=1: Wc_z+Whh_z, c=2: Wc_n, c=3: Whh_n
__global__ __launch_bounds__(256) void pack_wimg(const float* __restrict__ Wc,
                                                 const float* __restrict__ Whh) {
    int nt = blockIdx.x, kc = blockIdx.y, tid = threadIdx.x;
    char* dst = g_Wimg + ((size_t)nt * 16 + kc) * 16384;
    for (int u = tid; u < 512; u += 256) {
        int r = u >> 3, unit = u & 7;
        int jt = r >> 2, c = r & 3;
        int j = nt * 16 + jt;
        float v[8];
        if (c < 2) {
            const float* s1 = Wc  + (size_t)(c * HID + j) * HID + kc * 64 + unit * 8;
            const float* s2 = Whh + (size_t)(c * HID + j) * HID + kc * 64 + unit * 8;
            float4 a0 = *(const float4*)s1, a1 = *(const float4*)(s1 + 4);
            float4 b0 = *(const float4*)s2, b1 = *(const float4*)(s2 + 4);
            v[0] = a0.x + b0.x; v[1] = a0.y + b0.y; v[2] = a0.z + b0.z; v[3] = a0.w + b0.w;
            v[4] = a1.x + b1.x; v[5] = a1.y + b1.y; v[6] = a1.z + b1.z; v[7] = a1.w + b1.w;
        } else {
            const float* s1 = (c == 2 ? Wc : Whh) + (size_t)(2 * HID + j) * HID + kc * 64 + unit * 8;
            *(float4*)&v[0] = *(const float4*)s1;
            *(float4*)&v[4] = *(const float4*)(s1 + 4);
        }
        uint4 hi, lo; split8(v, hi, lo);
        uint32_t o = sw128((uint32_t)(r * 128 + unit * 16));
        *(uint4*)(dst + o) = hi;
        *(uint4*)(dst + 8192 + o) = lo;
    }
}

// W_fc images: nt(6) x kc(16): 128 rows x 64 k-cols
__global__ __launch_bounds__(256) void pack_wfcimg(const float* __restrict__ Wfc) {
    int nt = blockIdx.x, kc = blockIdx.y, tid = threadIdx.x;
    char* dst = g_Wfcimg + ((size_t)nt * 16 + kc) * 32768;
    for (int u = tid; u < 1024; u += 256) {
        int r = u >> 3, unit = u & 7;
        const float* srcrow = Wfc + (size_t)(nt * 128 + r) * HID + kc * 64 + unit * 8;
        float v[8];
        *(float4*)&v[0] = *(const float4*)srcrow;
        *(float4*)&v[4] = *(const float4*)(srcrow + 4);
        uint4 hi, lo; split8(v, hi, lo);
        uint32_t o = sw128((uint32_t)(r * 128 + unit * 16));
        *(uint4*)(dst + o) = hi;
        *(uint4*)(dst + 16384 + o) = lo;
    }
}

// h_1 (SIMT step 0 result) -> A image for t=1
__global__ __launch_bounds__(256) void h2img() {
    int mh = blockIdx.x, kc = blockIdx.y, tid = threadIdx.x;
    char* dst = g_Aimg + ((size_t)(1 * 2 + mh) * 16 + kc) * 32768;
    for (int u = tid; u < 1024; u += 256) {
        int r = u >> 3, unit = u & 7;
        const float* hp = g_H + ((size_t)1 * BATCH + mh * 128 + r) * HID + kc * 64 + unit * 8;
        float v[8];
        *(float4*)&v[0] = *(const float4*)hp;
        *(float4*)&v[4] = *(const float4*)(hp + 4);
        uint4 hi, lo; split8(v, hi, lo);
        uint32_t o = sw128((uint32_t)(r * 128 + unit * 16));
        *(uint4*)(dst + o) = hi;
        *(uint4*)(dst + 16384 + o) = lo;
    }
}

// ===========================================================================
// persistent HMMA recurrence: all steps in one launch, global barrier between.
// grid (64 nt, 2 mh) = 128 CTAs (1/SM, co-resident), 256 threads.
// per step: D[128 x 64] = h @ Wfused^T (bf16 hi/lo x3), gates, h image write.
// ===========================================================================
#define STG2 49152
#define PERSIST_DYN (3 * STG2)

__global__ __launch_bounds__(256, 1) void gru_persist(int t0, int T,
                                                      const float* __restrict__ bhh) {
    extern __shared__ char dsm[];
    uint32_t base = smem_u32(dsm);
    int tid = threadIdx.x;
    int wid = tid >> 5, lane = tid & 31;
    int nt = blockIdx.x, mh = blockIdx.y;
    int wm = wid & 3, wn = wid >> 2;

    const char* Bsrc = g_Wimg + (size_t)nt * (16 * 16384);

    for (int t = t0; t < T; t++) {
        const char* Asrc = g_Aimg + (size_t)(t * 2 + mh) * (16 * 32768);

        float acc[2][4][4];
#pragma unroll
        for (int a = 0; a < 2; a++)
#pragma unroll
            for (int b = 0; b < 4; b++)
#pragma unroll
                for (int cc = 0; cc < 4; cc++) acc[a][b][cc] = 0.f;

        // prologue: chunks 0,1 -> stages 0,1
#pragma unroll
        for (int pc = 0; pc < 2; pc++) {
            uint32_t d = base + pc * STG2;
            const char* ap = Asrc + (size_t)pc * 32768;
            const char* bp = Bsrc + (size_t)pc * 16384;
#pragma unroll
            for (int q = 0; q < 8; q++) cpa16(d + q * 4096 + tid * 16, ap + q * 4096 + tid * 16);
#pragma unroll
            for (int q = 0; q < 4; q++) cpa16(d + 32768 + q * 4096 + tid * 16, bp + q * 4096 + tid * 16);
            CP_COMMIT();
        }

        for (int c = 0; c < 16; c++) {
            if (c == 15) { CP_WAIT(0); } else { CP_WAIT(1); }
            __syncthreads();
            if (c + 2 < 16) {
                int s2 = (c + 2) % 3;
                uint32_t d = base + s2 * STG2;
                const char* ap = Asrc + (size_t)(c + 2) * 32768;
                const char* bp = Bsrc + (size_t)(c + 2) * 16384;
#pragma unroll
                for (int q = 0; q < 8; q++) cpa16(d + q * 4096 + tid * 16, ap + q * 4096 + tid * 16);
#pragma unroll
                for (int q = 0; q < 4; q++) cpa16(d + 32768 + q * 4096 + tid * 16, bp + q * 4096 + tid * 16);
                CP_COMMIT();
            }
            uint32_t sA = base + (c % 3) * STG2;
            uint32_t sB = sA + 32768;
#pragma unroll
            for (int kk = 0; kk < 4; kk++) {
                uint32_t ah[2][4], al[2][4], bh[2][4], bl[2][4];
                int seg = kk * 32 + (lane >> 4) * 16;
#pragma unroll
                for (int mt = 0; mt < 2; mt++) {
                    int r = wm * 32 + mt * 16 + (lane & 15);
                    uint32_t off = sw128((uint32_t)(r * 128 + seg));
                    ldsm4(ah[mt], sA + off);
                    ldsm4(al[mt], sA + 16384 + off);
                }
#pragma unroll
                for (int nq = 0; nq < 2; nq++) {
                    int r = wn * 32 + nq * 16 + (lane & 15);
                    uint32_t off = sw128((uint32_t)(r * 128 + seg));
                    ldsm4(bh[nq], sB + off);
                    ldsm4(bl[nq], sB + 8192 + off);
                }
#pragma unroll
                for (int mt = 0; mt < 2; mt++)
#pragma unroll
                    for (int n8 = 0; n8 < 4; n8++) {
                        int nq = n8 >> 1, hf = n8 & 1;
                        mma16816(acc[mt][n8], ah[mt], bh[nq][hf], bh[nq][hf + 2]);
                        mma16816(acc[mt][n8], ah[mt], bl[nq][hf], bl[nq][hf + 2]);
                        mma16816(acc[mt][n8], al[mt], bh[nq][hf], bh[nq][hf + 2]);
                    }
            }
        }

        // ---- epilogue ----
        __syncthreads();
        float* sf = (float*)dsm;
#pragma unroll
        for (int mt = 0; mt < 2; mt++)
#pragma unroll
            for (int n8 = 0; n8 < 4; n8++) {
                int r0 = wm * 32 + mt * 16 + (lane >> 2);
                int c0 = wn * 32 + n8 * 8 + 2 * (lane & 3);
                *(float2*)&sf[r0 * 68 + c0]       = make_float2(acc[mt][n8][0], acc[mt][n8][1]);
                *(float2*)&sf[(r0 + 8) * 68 + c0] = make_float2(acc[mt][n8][2], acc[mt][n8][3]);
            }
        __syncthreads();

        int r = tid >> 1, uh = tid & 1;
        int b = mh * 128 + r;
        int j0 = nt * 16 + uh * 8;
        const float* hprev = g_H + ((size_t)t * BATCH + b) * HID + j0;
        float* hnew = g_H + ((size_t)(t + 1) * BATCH + b) * HID + j0;
        float hp[8], hv[8];
        *(float4*)&hp[0] = *(const float4*)(hprev);
        *(float4*)&hp[4] = *(const float4*)(hprev + 4);
#pragma unroll
        for (int i = 0; i < 8; i++) {
            const float* g4 = &sf[r * 68 + (uh * 8 + i) * 4];
            int j = j0 + i;
            float rg = sigmf(g4[0] + g_bcomb[j] + bhh[j]);
            float zg = sigmf(g4[1] + g_bcomb[HID + j] + bhh[HID + j]);
            float ng = tanhf(g4[2] + g_bcomb[2 * HID + j] + rg * (g4[3] + bhh[2 * HID + j]));
            hv[i] = (1.f - zg) * ng + zg * hp[i];
        }
        *(float4*)(hnew)     = *(float4*)&hv[0];
        *(float4*)(hnew + 4) = *(float4*)&hv[4];

        uint4 hi, lo;
        split8(hv, hi, lo);
        char* dst = g_Aimg + ((size_t)((t + 1) * 2 + mh) * 16 + (nt >> 2)) * 32768;
        uint32_t o = sw128((uint32_t)(r * 128 + (nt & 3) * 32 + uh * 16));
        *(uint4*)(dst + o) = hi;
        *(uint4*)(dst + 16384 + o) = lo;

        // ---- global barrier (skip after final step) ----
        if (t + 1 < T) {
            __threadfence();
            __syncthreads();
            if (tid == 0) {
                atomicAdd((unsigned*)&g_bar, 1u);
                unsigned tgt = 128u * (unsigned)(t - t0 + 1);
                while (g_bar < tgt) { }
                __threadfence();
            }
            __syncthreads();
        }
    }
}

// ===========================================================================
// HMMA output GEMM: Y[(t-1)*256+b][o] = h_t @ Wfc^T + bfc
// grid (6 nt, 2 mh, T), 256 threads
// ===========================================================================
#define OSTG 65536
#define OUT_DYN (2 * OSTG)

__global__ __launch_bounds__(256, 1) void out_gemm_mma(float* __restrict__ out,
                                                       const float* __restrict__ bfc) {
    extern __shared__ char dsm[];
    uint32_t base = smem_u32(dsm);
    int tid = threadIdx.x;
    int wid = tid >> 5, lane = tid & 31;
    int nt = blockIdx.x, mh = blockIdx.y;
    int t = blockIdx.z + 1;
    int wm = wid & 3, wn = wid >> 2;

    const char* Asrc = g_Aimg + (size_t)(t * 2 + mh) * (16 * 32768);
    const char* Bsrc = g_Wfcimg + (size_t)nt * (16 * 32768);

    float acc[2][8][4];
#pragma unroll
    for (int a = 0; a < 2; a++)
#pragma unroll
        for (int b = 0; b < 8; b++)
#pragma unroll
            for (int c = 0; c < 4; c++) acc[a][b][c] = 0.f;

    {
        uint32_t d = base;
#pragma unroll
        for (int q = 0; q < 8; q++) cpa16(d + q * 4096 + tid * 16, Asrc + q * 4096 + tid * 16);
#pragma unroll
        for (int q = 0; q < 8; q++) cpa16(d + 32768 + q * 4096 + tid * 16, Bsrc + q * 4096 + tid * 16);
        CP_COMMIT();
    }

    for (int c = 0; c < 16; c++) {
        if (c < 15) {
            uint32_t d = base + ((c + 1) & 1) * OSTG;
            const char* ap = Asrc + (size_t)(c + 1) * 32768;
            const char* bp = Bsrc + (size_t)(c + 1) * 32768;
#pragma unroll
            for (int q = 0; q < 8; q++) cpa16(d + q * 4096 + tid * 16, ap + q * 4096 + tid * 16);
#pragma unroll
            for (int q = 0; q < 8; q++) cpa16(d + 32768 + q * 4096 + tid * 16, bp + q * 4096 + tid * 16);
            CP_COMMIT();
            CP_WAIT(1);
        } else {
            CP_WAIT(0);
        }
        __syncthreads();
        uint32_t sA = base + (c & 1) * OSTG;
        uint32_t sB = sA + 32768;
#pragma unroll
        for (int kk = 0; kk < 4; kk++) {
            uint32_t ah[2][4], al[2][4], bh[4][4], bl[4][4];
            int seg = kk * 32 + (lane >> 4) * 16;
#pragma unroll
            for (int mt = 0; mt < 2; mt++) {
                int r = wm * 32 + mt * 16 + (lane & 15);
                uint32_t off = sw128((uint32_t)(r * 128 + seg));
                ldsm4(ah[mt], sA + off);
                ldsm4(al[mt], sA + 16384 + off);
            }
#pragma unroll
            for (int nq = 0; nq < 4; nq++) {
                int r = wn * 64 + nq * 16 + (lane & 15);
                uint32_t off = sw128((uint32_t)(r * 128 + seg));
                ldsm4(bh[nq], sB + off);
                ldsm4(bl[nq], sB + 16384 + off);
            }
#pragma unroll
            for (int mt = 0; mt < 2; mt++)
#pragma unroll
                for (int n8 = 0; n8 < 8; n8++) {
                    int nq = n8 >> 1, hf = n8 & 1;
                    mma16816(acc[mt][n8], ah[mt], bh[nq][hf], bh[nq][hf + 2]);
                    mma16816(acc[mt][n8], ah[mt], bl[nq][hf], bl[nq][hf + 2]);
                    mma16816(acc[mt][n8], al[mt], bh[nq][hf], bh[nq][hf + 2]);
                }
        }
        __syncthreads();
    }

    size_t row0 = (size_t)(t - 1) * BATCH + mh * 128;
#pragma unroll
    for (int mt = 0; mt < 2; mt++)
#pragma unroll
        for (int n8 = 0; n8 < 8; n8++) {
            int rr = wm * 32 + mt * 16 + (lane >> 2);
            int cc = nt * 128 + wn * 64 + n8 * 8 + 2 * (lane & 3);
            float2 bv = *(const float2*)(bfc + cc);
            float2 v0 = make_float2(acc[mt][n8][0] + bv.x, acc[mt][n8][1] + bv.y);
            float2 v1 = make_float2(acc[mt][n8][2] + bv.x, acc[mt][n8][3] + bv.y);
            *(float2*)(out + (row0 + rr) * OUTD + cc)     = v0;
            *(float2*)(out + (row0 + rr + 8) * OUTD + cc) = v1;
        }
}

// ===========================================================================
extern "C" void kernel_launch(void* const* d_in, const int* in_sizes, int n_in,
                              void* d_out, int out_size) {
    const float* src    = (const float*)d_in[0];
    const float* hidden = (const float*)d_in[2];
    const float* W_ih   = (const float*)d_in[3];
    const float* W_hh   = (const float*)d_in[4];
    const float* b_ih   = (const float*)d_in[5];
    const float* b_hh   = (const float*)d_in[6];
    const float* W_fc   = (const float*)d_in[7];
    const float* b_fc   = (const float*)d_in[8];
    float* out = (float*)d_out;

    int T = out_size / (BATCH * OUTD);
    if (T > TMAX) T = TMAX;
    if (T < 1) T = 1;

    float *pH, *pWihf, *pWhhf, *pWc, *pbc;
    cudaGetSymbolAddress((void**)&pH, g_H);
    cudaGetSymbolAddress((void**)&pWihf, g_Wih_f);
    cudaGetSymbolAddress((void**)&pWhhf, g_Whh_f);
    cudaGetSymbolAddress((void**)&pWc, g_Wc);
    cudaGetSymbolAddress((void**)&pbc, g_bcomb);

    cudaFuncSetAttribute(gru_persist, cudaFuncAttributeMaxDynamicSharedMemorySize, PERSIST_DYN);
    cudaFuncSetAttribute(out_gemm_mma, cudaFuncAttributeMaxDynamicSharedMemorySize, OUT_DYN);

    // --- precompute ---
    zero_bar<<<1, 1>>>();
    pack_w<<<dim3(OUTD / 32, NJB, 3), 256>>>(pWihf, W_ih, OUTD);
    pack_w<<<dim3(HID / 32, NJB, 3), 256>>>(pWhhf, W_hh, HID);
    gemm_nn<<<dim3(HID / 64, (3 * HID) / 128), 256>>>(W_ih, W_fc, nullptr, pWc,
                                                      3 * HID, HID, OUTD);
    bcomb_k<<<(3 * HID) / 8, 256>>>(W_ih, b_fc, b_ih, pbc);
    copy_f<<<(BATCH * HID / 4 + 255) / 256, 256>>>(pH, hidden, BATCH * HID / 4);
    pack_wimg<<<dim3(64, 16), 256>>>(pWc, W_hh);
    pack_wfcimg<<<dim3(6, 16), 256>>>(W_fc);

    // --- step 0 (SIMT, K=768 input path) ---
    gru_step<<<dim3(NJB, BATCH / 64), 256>>>(src, OUTD, pWihf, b_ih,
                                             pH, pWhhf, b_hh,
                                             pH + (size_t)BATCH * HID);
    h2img<<<dim3(2, 16), 256>>>();

    // --- persistent HMMA recurrence (steps 1..T-1 in ONE launch) ---
    if (T > 1)
        gru_persist<<<dim3(64, 2), 256, PERSIST_DYN>>>(1, T, b_hh);

    // --- HMMA output projection ---
    out_gemm_mma<<<dim3(6, 2, T), 256, OUT_DYN>>>(out, b_fc);
}

// round 8
// speedup vs baseline: 1.5827x; 1.2321x over previous
#include <cuda_runtime.h>
#include <cuda_fp16.h>
#include <math.h>
#include <stdint.h>

#define HID   1024
#define OUTD  768
#define BATCH 256
#define TMAX  256
#define NJB   (HID / 32)

// ===========================================================================
// helpers
// ===========================================================================
__device__ __forceinline__ uint32_t smem_u32(const void* p) {
    uint32_t a;
    asm("{ .reg .u64 t; cvta.to.shared.u64 t, %1; cvt.u32.u64 %0, t; }" : "=r"(a) : "l"(p));
    return a;
}
__device__ __host__ __forceinline__ uint32_t sw128(uint32_t off) {
    return off ^ ((off >> 3) & 0x70);
}
__device__ __forceinline__ void cpa16(uint32_t dst, const void* src) {
    asm volatile("cp.async.cg.shared.global [%0], [%1], 16;" :: "r"(dst), "l"(src));
}
#define CP_COMMIT() asm volatile("cp.async.commit_group;" ::: "memory")
#define CP_WAIT(n)  asm volatile("cp.async.wait_group %0;" :: "n"(n) : "memory")

__device__ __forceinline__ void ldsm4(uint32_t (&r)[4], uint32_t addr) {
    asm volatile("ldmatrix.sync.aligned.m8n8.x4.shared.b16 {%0,%1,%2,%3}, [%4];"
        : "=r"(r[0]), "=r"(r[1]), "=r"(r[2]), "=r"(r[3]) : "r"(addr));
}
__device__ __forceinline__ void mma16816h(float (&d)[4], const uint32_t (&a)[4],
                                          uint32_t b0, uint32_t b1) {
    asm volatile("mma.sync.aligned.m16n8k16.row.col.f32.f16.f16.f32 "
        "{%0,%1,%2,%3}, {%4,%5,%6,%7}, {%8,%9}, {%0,%1,%2,%3};"
        : "+f"(d[0]), "+f"(d[1]), "+f"(d[2]), "+f"(d[3])
        : "r"(a[0]), "r"(a[1]), "r"(a[2]), "r"(a[3]), "r"(b0), "r"(b1));
}

// ===========================================================================
// device scratch
// ===========================================================================
__device__ float g_H[(TMAX + 1) * BATCH * HID];
__device__ float g_Wih_f[NJB * OUTD * 3 * 32];
__device__ float g_Whh_f[NJB * HID * 3 * 32];
__device__ float g_Wc[3 * HID * HID];
__device__ float g_bcomb[3 * HID];
__device__ unsigned g_barm[2];
__device__ volatile unsigned g_stepm[2];
__device__ unsigned g_outq;
// fp16 SW128 tile images
__device__ __align__(1024) char g_Aimg[(size_t)(TMAX + 1) * 2 * 16 * 16384]; // [t][mh][kc] 128x64 fp16
__device__ __align__(1024) char g_Wimg[(size_t)64 * 16 * 16384];             // [nt][kc]{hi8K,lo8K}
__device__ __align__(1024) char g_Wfcimg[(size_t)6 * 16 * 32768];            // [nt][kc]{hi16K,lo16K}

// ===========================================================================
// fp32 SIMT pieces (step 0 + W_comb precompute)
// ===========================================================================
__device__ __forceinline__ unsigned long long dup2(float x) {
    unsigned long long r;
    asm("mov.b64 %0, {%1, %1};" : "=l"(r) : "f"(x));
    return r;
}
__device__ __forceinline__ void fmax2(unsigned long long& d, unsigned long long a,
                                      unsigned long long b) {
    asm("fma.rn.f32x2 %0, %1, %2, %0;" : "+l"(d) : "l"(a), "l"(b));
}
union F4U { float4 f; unsigned long long u[2]; };
union U2F { unsigned long long u; float2 f; };
__device__ __forceinline__ float sigmf(float x) { return 1.0f / (1.0f + __expf(-x)); }

__global__ __launch_bounds__(256) void pack_w(float* __restrict__ dst,
                                              const float* __restrict__ src, int Ks) {
    __shared__ float sm[32][33];
    int k0 = blockIdx.x * 32, jb = blockIdx.y, g = blockIdx.z, t = threadIdx.x;
    int jl = t >> 3, kq = t & 7;
    float4 v = *(const float4*)(src + (size_t)(g * HID + jb * 32 + jl) * Ks + k0 + kq * 4);
    sm[jl][kq * 4 + 0] = v.x; sm[jl][kq * 4 + 1] = v.y;
    sm[jl][kq * 4 + 2] = v.z; sm[jl][kq * 4 + 3] = v.w;
    __syncthreads();
    int ji = t & 31, kk0 = t >> 5;
#pragma unroll
    for (int r = 0; r < 4; r++) {
        int kk = kk0 + r * 8;
        dst[(((size_t)jb * Ks + k0 + kk) * 3 + g) * 32 + ji] = sm[ji][kk];
    }
}

__global__ __launch_bounds__(256) void bcomb_k(const float* __restrict__ Wih,
                                               const float* __restrict__ bfc,
                                               const float* __restrict__ bih,
                                               float* __restrict__ out) {
    int j = blockIdx.x * 8 + (threadIdx.x >> 5);
    int lane = threadIdx.x & 31;
    float s = 0.f;
    for (int o = lane; o < OUTD; o += 32) s += Wih[(size_t)j * OUTD + o] * bfc[o];
#pragma unroll
    for (int off = 16; off; off >>= 1) s += __shfl_xor_sync(0xffffffffu, s, off);
    if (lane == 0) out[j] = s + bih[j];
}

__global__ __launch_bounds__(256) void copy_f(float* __restrict__ dst,
                                              const float* __restrict__ src, int n4) {
    int i = blockIdx.x * 256 + threadIdx.x;
    if (i < n4) ((float4*)dst)[i] = ((const float4*)src)[i];
}

__global__ void init_sync() {
    g_barm[0] = 0; g_barm[1] = 0;
    g_stepm[0] = 1; g_stepm[1] = 1;
    g_outq = 0;
}

__global__ __launch_bounds__(256) void gemm_nn(const float* __restrict__ A,
                                               const float* __restrict__ B,
                                               const float* __restrict__ bias,
                                               float* __restrict__ C,
                                               int M, int N, int K) {
    __shared__ float2 sA[32][66];
    __shared__ float  sB[32][64];
    int n0 = blockIdx.x * 64, m0 = blockIdx.y * 128, t = threadIdx.x;
    int tn = t & 15, tm = t >> 4;
    unsigned long long acc[4][4] = {};
    float4 ast[4], bst[2];
#pragma unroll
    for (int r = 0; r < 4; r++) {
        int idx = t + 256 * r, m = idx >> 3, kf = idx & 7;
        ast[r] = *(const float4*)(A + (size_t)(m0 + m) * K + kf * 4);
    }
#pragma unroll
    for (int r = 0; r < 2; r++) {
        int idx = t + 256 * r, kk = idx >> 4, nf = idx & 15;
        bst[r] = *(const float4*)(B + (size_t)kk * N + n0 + nf * 4);
    }
    int nch = K >> 5;
    for (int ch = 0; ch < nch; ch++) {
        float* sp = (float*)&sA[0][0];
#pragma unroll
        for (int r = 0; r < 4; r++) {
            int idx = t + 256 * r, m = idx >> 3, kf = idx & 7;
            sp[(kf * 4 + 0) * 132 + m] = ast[r].x; sp[(kf * 4 + 1) * 132 + m] = ast[r].y;
            sp[(kf * 4 + 2) * 132 + m] = ast[r].z; sp[(kf * 4 + 3) * 132 + m] = ast[r].w;
        }
#pragma unroll
        for (int r = 0; r < 2; r++) {
            int idx = t + 256 * r, kk = idx >> 4, nf = idx & 15;
            *(float4*)&sB[kk][nf * 4] = bst[r];
        }
        __syncthreads();
        if (ch + 1 < nch) {
            int k0 = (ch + 1) * 32;
#pragma unroll
            for (int r = 0; r < 4; r++) {
                int idx = t + 256 * r, m = idx >> 3, kf = idx & 7;
                ast[r] = *(const float4*)(A + (size_t)(m0 + m) * K + k0 + kf * 4);
            }
#pragma unroll
            for (int r = 0; r < 2; r++) {
                int idx = t + 256 * r, kk = idx >> 4, nf = idx & 15;
                bst[r] = *(const float4*)(B + (size_t)(k0 + kk) * N + n0 + nf * 4);
            }
        }
#pragma unroll 8
        for (int k = 0; k < 32; k++) {
            F4U a0, a1, bv;
            a0.f = *(const float4*)&sA[k][tm * 4];
            a1.f = *(const float4*)&sA[k][tm * 4 + 2];
            bv.f = *(const float4*)&sB[k][tn * 4];
            unsigned long long d0 = dup2(bv.f.x), d1 = dup2(bv.f.y),
                               d2 = dup2(bv.f.z), d3 = dup2(bv.f.w);
            fmax2(acc[0][0], a0.u[0], d0); fmax2(acc[0][1], a0.u[1], d0);
            fmax2(acc[0][2], a1.u[0], d0); fmax2(acc[0][3], a1.u[1], d0);
            fmax2(acc[1][0], a0.u[0], d1); fmax2(acc[1][1], a0.u[1], d1);
            fmax2(acc[1][2], a1.u[0], d1); fmax2(acc[1][3], a1.u[1], d1);
            fmax2(acc[2][0], a0.u[0], d2); fmax2(acc[2][1], a0.u[1], d2);
            fmax2(acc[2][2], a1.u[0], d2); fmax2(acc[2][3], a1.u[1], d2);
            fmax2(acc[3][0], a0.u[0], d3); fmax2(acc[3][1], a0.u[1], d3);
            fmax2(acc[3][2], a1.u[0], d3); fmax2(acc[3][3], a1.u[1], d3);
        }
        __syncthreads();
    }
#pragma unroll
    for (int ni = 0; ni < 4; ni++) {
        int n = n0 + tn * 4 + ni;
        float bv = bias ? bias[n] : 0.f;
#pragma unroll
        for (int p = 0; p < 4; p++) {
            U2F v; v.u = acc[ni][p];
            int m = m0 + tm * 8 + p * 2;
            C[(size_t)m * N + n] = v.f.x + bv;
            C[(size_t)(m + 1) * N + n] = v.f.y + bv;
        }
    }
}

// SIMT GRU step (step 0 only)
__device__ __forceinline__ void gru_phase(unsigned long long (&acc)[3][4],
                                          const float* __restrict__ src, int Kd,
                                          const float* __restrict__ Wf,
                                          int jb, int b0, int t, int tx, int ty,
                                          float* sW, float2 (*sH)[34]) {
    const float* Wp = Wf + (size_t)jb * Kd * 96;
    int nch = Kd >> 5;
    float4 wst0, wst1, wst2, hst0, hst1;
    {
        const float4* wp4 = (const float4*)Wp;
        wst0 = wp4[t]; wst1 = wp4[t + 256]; wst2 = wp4[t + 512];
        int i0 = t, i1 = t + 256;
        hst0 = *(const float4*)(src + (size_t)(b0 + (i0 >> 3)) * Kd + ((i0 & 7) << 2));
        hst1 = *(const float4*)(src + (size_t)(b0 + (i1 >> 3)) * Kd + ((i1 & 7) << 2));
    }
    for (int ch = 0; ch < nch; ch++) {
        ((float4*)sW)[t] = wst0; ((float4*)sW)[t + 256] = wst1; ((float4*)sW)[t + 512] = wst2;
        float* sp = (float*)&sH[0][0];
        {
            int m = t >> 3, kf = t & 7;
            sp[(kf * 4 + 0) * 68 + m] = hst0.x; sp[(kf * 4 + 1) * 68 + m] = hst0.y;
            sp[(kf * 4 + 2) * 68 + m] = hst0.z; sp[(kf * 4 + 3) * 68 + m] = hst0.w;
            int i1 = t + 256; m = i1 >> 3; kf = i1 & 7;
            sp[(kf * 4 + 0) * 68 + m] = hst1.x; sp[(kf * 4 + 1) * 68 + m] = hst1.y;
            sp[(kf * 4 + 2) * 68 + m] = hst1.z; sp[(kf * 4 + 3) * 68 + m] = hst1.w;
        }
        __syncthreads();
        if (ch + 1 < nch) {
            int k0 = (ch + 1) * 32;
            const float4* wp4 = (const float4*)(Wp + (size_t)k0 * 96);
            wst0 = wp4[t]; wst1 = wp4[t + 256]; wst2 = wp4[t + 512];
            int i0 = t, i1 = t + 256;
            hst0 = *(const float4*)(src + (size_t)(b0 + (i0 >> 3)) * Kd + k0 + ((i0 & 7) << 2));
            hst1 = *(const float4*)(src + (size_t)(b0 + (i1 >> 3)) * Kd + k0 + ((i1 & 7) << 2));
        }
#pragma unroll 8
        for (int k = 0; k < 32; k++) {
            F4U a0, a1;
            a0.f = *(const float4*)&sH[k][ty * 4];
            a1.f = *(const float4*)&sH[k][ty * 4 + 2];
            float w0 = sW[k * 96 + tx], w1 = sW[k * 96 + 32 + tx], w2 = sW[k * 96 + 64 + tx];
            unsigned long long d0 = dup2(w0), d1 = dup2(w1), d2 = dup2(w2);
            fmax2(acc[0][0], a0.u[0], d0); fmax2(acc[0][1], a0.u[1], d0);
            fmax2(acc[0][2], a1.u[0], d0); fmax2(acc[0][3], a1.u[1], d0);
            fmax2(acc[1][0], a0.u[0], d1); fmax2(acc[1][1], a0.u[1], d1);
            fmax2(acc[1][2], a1.u[0], d1); fmax2(acc[1][3], a1.u[1], d1);
            fmax2(acc[2][0], a0.u[0], d2); fmax2(acc[2][1], a0.u[1], d2);
            fmax2(acc[2][2], a1.u[0], d2); fmax2(acc[2][3], a1.u[1], d2);
        }
        __syncthreads();
    }
}

__global__ __launch_bounds__(256) void gru_step(const float* __restrict__ inp, int Ki,
                                                const float* __restrict__ Wi,
                                                const float* __restrict__ bi,
                                                const float* __restrict__ hin,
                                                const float* __restrict__ Wh,
                                                const float* __restrict__ bh,
                                                float* __restrict__ hout) {
    __shared__ float  sW[32 * 96];
    __shared__ float2 sH[32][34];
    int jb = blockIdx.x, b0 = blockIdx.y * 64, t = threadIdx.x;
    int tx = t & 31, ty = t >> 5;
    unsigned long long acci[3][4] = {};
    unsigned long long acch[3][4] = {};
    gru_phase(acci, inp, Ki, Wi, jb, b0, t, tx, ty, sW, sH);
    gru_phase(acch, hin, HID, Wh, jb, b0, t, tx, ty, sW, sH);
    int j = jb * 32 + tx;
    float bir = bi[j], bhr = bh[j];
    float biz = bi[HID + j], bhz = bh[HID + j];
    float bin_ = bi[2 * HID + j], bhn = bh[2 * HID + j];
#pragma unroll
    for (int p = 0; p < 4; p++) {
        U2F ir, iz, in_, hr, hz, hn;
        ir.u = acci[0][p]; iz.u = acci[1][p]; in_.u = acci[2][p];
        hr.u = acch[0][p]; hz.u = acch[1][p]; hn.u = acch[2][p];
        int b = b0 + ty * 8 + p * 2;
        float r0 = sigmf(ir.f.x + bir + hr.f.x + bhr);
        float z0 = sigmf(iz.f.x + biz + hz.f.x + bhz);
        float n0 = tanhf(in_.f.x + bin_ + r0 * (hn.f.x + bhn));
        float hp0 = hin[(size_t)b * HID + j];
        hout[(size_t)b * HID + j] = (1.f - z0) * n0 + z0 * hp0;
        float r1 = sigmf(ir.f.y + bir + hr.f.y + bhr);
        float z1 = sigmf(iz.f.y + biz + hz.f.y + bhz);
        float n1 = tanhf(in_.f.y + bin_ + r1 * (hn.f.y + bhn));
        float hp1 = hin[(size_t)(b + 1) * HID + j];
        hout[(size_t)(b + 1) * HID + j] = (1.f - z1) * n1 + z1 * hp1;
    }
}

// ===========================================================================
// fp16 split + packers
// ===========================================================================
union BPK { unsigned short s[8]; uint4 v; };
__device__ __forceinline__ void split8h(const float* v, uint4& hi, uint4& lo) {
    BPK ph, pl;
#pragma unroll
    for (int i = 0; i < 8; i++) {
        __half a = __float2half(v[i]);
        float r = v[i] - __half2float(a);
        __half b = __float2half(r);
        ph.s[i] = *(unsigned short*)&a;
        pl.s[i] = *(unsigned short*)&b;
    }
    hi = ph.v; lo = pl.v;
}
__device__ __forceinline__ uint4 cvt8h(const float* v) {
    BPK p;
#pragma unroll
    for (int i = 0; i < 8; i++) {
        __half a = __float2half(v[i]);
        p.s[i] = *(unsigned short*)&a;
    }
    return p.v;
}

// Gate-fused W images (fp16 hi/lo): nt(64) x kc(16): 64 rows x 64 k
// row = jt*4 + c;  c=0: Wc_r+Whh_r, c=1: Wc_z+Whh_z, c=2: Wc_n, c=3: Whh_n
__global__ __launch_bounds__(256) void pack_wimg(const float* __restrict__ Wc,
                                                 const float* __restrict__ Whh) {
    int nt = blockIdx.x, kc = blockIdx.y, tid = threadIdx.x;
    char* dst = g_Wimg + ((size_t)nt * 16 + kc) * 16384;
    for (int u = tid; u < 512; u += 256) {
        int r = u >> 3, unit = u & 7;
        int jt = r >> 2, c = r & 3;
        int j = nt * 16 + jt;
        float v[8];
        if (c < 2) {
            const float* s1 = Wc  + (size_t)(c * HID + j) * HID + kc * 64 + unit * 8;
            const float* s2 = Whh + (size_t)(c * HID + j) * HID + kc * 64 + unit * 8;
            float4 a0 = *(const float4*)s1, a1 = *(const float4*)(s1 + 4);
            float4 b0 = *(const float4*)s2, b1 = *(const float4*)(s2 + 4);
            v[0] = a0.x + b0.x; v[1] = a0.y + b0.y; v[2] = a0.z + b0.z; v[3] = a0.w + b0.w;
            v[4] = a1.x + b1.x; v[5] = a1.y + b1.y; v[6] = a1.z + b1.z; v[7] = a1.w + b1.w;
        } else {
            const float* s1 = (c == 2 ? Wc : Whh) + (size_t)(2 * HID + j) * HID + kc * 64 + unit * 8;
            *(float4*)&v[0] = *(const float4*)s1;
            *(float4*)&v[4] = *(const float4*)(s1 + 4);
        }
        uint4 hi, lo; split8h(v, hi, lo);
        uint32_t o = sw128((uint32_t)(r * 128 + unit * 16));
        *(uint4*)(dst + o) = hi;
        *(uint4*)(dst + 8192 + o) = lo;
    }
}

// W_fc images (fp16 hi/lo): nt(6) x kc(16): 128 rows x 64 k
__global__ __launch_bounds__(256) void pack_wfcimg(const float* __restrict__ Wfc) {
    int nt = blockIdx.x, kc = blockIdx.y, tid = threadIdx.x;
    char* dst = g_Wfcimg + ((size_t)nt * 16 + kc) * 32768;
    for (int u = tid; u < 1024; u += 256) {
        int r = u >> 3, unit = u & 7;
        const float* srcrow = Wfc + (size_t)(nt * 128 + r) * HID + kc * 64 + unit * 8;
        float v[8];
        *(float4*)&v[0] = *(const float4*)srcrow;
        *(float4*)&v[4] = *(const float4*)(srcrow + 4);
        uint4 hi, lo; split8h(v, hi, lo);
        uint32_t o = sw128((uint32_t)(r * 128 + unit * 16));
        *(uint4*)(dst + o) = hi;
        *(uint4*)(dst + 16384 + o) = lo;
    }
}

// h_1 -> fp16 A image for t=1
__global__ __launch_bounds__(256) void h2img() {
    int mh = blockIdx.x, kc = blockIdx.y, tid = threadIdx.x;
    char* dst = g_Aimg + ((size_t)(1 * 2 + mh) * 16 + kc) * 16384;
    for (int u = tid; u < 1024; u += 256) {
        int r = u >> 3, unit = u & 7;
        const float* hp = g_H + ((size_t)1 * BATCH + mh * 128 + r) * HID + kc * 64 + unit * 8;
        float v[8];
        *(float4*)&v[0] = *(const float4*)hp;
        *(float4*)&v[4] = *(const float4*)(hp + 4);
        uint32_t o = sw128((uint32_t)(r * 128 + unit * 16));
        *(uint4*)(dst + o) = cvt8h(v);
    }
}

// ===========================================================================
// über-kernel: 148 CTAs. bid<128: persistent recurrence (then join out queue);
// bid>=128: out-tile workers from the start.
// ===========================================================================
#define RSTG 32768   // A 16K + B 16K (fp16 2-product, K=64 chunk)
#define OSTG 49152   // A 16K + B 32K
#define UBER_DYN 122880  // > 113KB forces 1 CTA/SM (co-residency for barrier)

__device__ __forceinline__ void rec_step(uint32_t base, char* dsm, int t, int nt, int mh,
                                         int tid, const float* __restrict__ bhh) {
    int wid = tid >> 5, lane = tid & 31;
    int wm = wid & 3, wn = wid >> 2;
    const char* Asrc = g_Aimg + (size_t)(t * 2 + mh) * (16 * 16384);
    const char* Bsrc = g_Wimg + (size_t)nt * (16 * 16384);

    float acc[2][4][4];
#pragma unroll
    for (int a = 0; a < 2; a++)
#pragma unroll
        for (int b = 0; b < 4; b++)
#pragma unroll
            for (int cc = 0; cc < 4; cc++) acc[a][b][cc] = 0.f;

#pragma unroll
    for (int pc = 0; pc < 2; pc++) {
        uint32_t d = base + pc * RSTG;
#pragma unroll
        for (int q = 0; q < 4; q++) {
            cpa16(d + q * 4096 + tid * 16, Asrc + (size_t)pc * 16384 + q * 4096 + tid * 16);
            cpa16(d + 16384 + q * 4096 + tid * 16, Bsrc + (size_t)pc * 16384 + q * 4096 + tid * 16);
        }
        CP_COMMIT();
    }

    for (int c = 0; c < 16; c++) {
        if (c == 15) { CP_WAIT(0); } else { CP_WAIT(1); }
        __syncthreads();
        if (c + 2 < 16) {
            uint32_t d = base + ((c + 2) % 3) * RSTG;
#pragma unroll
            for (int q = 0; q < 4; q++) {
                cpa16(d + q * 4096 + tid * 16, Asrc + (size_t)(c + 2) * 16384 + q * 4096 + tid * 16);
                cpa16(d + 16384 + q * 4096 + tid * 16, Bsrc + (size_t)(c + 2) * 16384 + q * 4096 + tid * 16);
            }
            CP_COMMIT();
        }
        uint32_t sA = base + (c % 3) * RSTG;
        uint32_t sB = sA + 16384;
#pragma unroll
        for (int kk = 0; kk < 4; kk++) {
            uint32_t ah[2][4], bh[2][4], bl[2][4];
            int seg = kk * 32 + (lane >> 4) * 16;
#pragma unroll
            for (int mt = 0; mt < 2; mt++) {
                int r = wm * 32 + mt * 16 + (lane & 15);
                ldsm4(ah[mt], sA + sw128((uint32_t)(r * 128 + seg)));
            }
#pragma unroll
            for (int nq = 0; nq < 2; nq++) {
                int r = wn * 32 + nq * 16 + (lane & 15);
                uint32_t off = sw128((uint32_t)(r * 128 + seg));
                ldsm4(bh[nq], sB + off);
                ldsm4(bl[nq], sB + 8192 + off);
            }
#pragma unroll
            for (int mt = 0; mt < 2; mt++)
#pragma unroll
                for (int n8 = 0; n8 < 4; n8++) {
                    int nq = n8 >> 1, hf = n8 & 1;
                    mma16816h(acc[mt][n8], ah[mt], bh[nq][hf], bh[nq][hf + 2]);
                    mma16816h(acc[mt][n8], ah[mt], bl[nq][hf], bl[nq][hf + 2]);
                }
        }
    }

    __syncthreads();
    float* sf = (float*)dsm;
#pragma unroll
    for (int mt = 0; mt < 2; mt++)
#pragma unroll
        for (int n8 = 0; n8 < 4; n8++) {
            int r0 = wm * 32 + mt * 16 + (lane >> 2);
            int c0 = wn * 32 + n8 * 8 + 2 * (lane & 3);
            *(float2*)&sf[r0 * 68 + c0]       = make_float2(acc[mt][n8][0], acc[mt][n8][1]);
            *(float2*)&sf[(r0 + 8) * 68 + c0] = make_float2(acc[mt][n8][2], acc[mt][n8][3]);
        }
    __syncthreads();

    int r = tid >> 1, uh = tid & 1;
    int b = mh * 128 + r;
    int j0 = nt * 16 + uh * 8;
    const float* hprev = g_H + ((size_t)t * BATCH + b) * HID + j0;
    float* hnew = g_H + ((size_t)(t + 1) * BATCH + b) * HID + j0;
    float hp[8], hv[8];
    *(float4*)&hp[0] = *(const float4*)(hprev);
    *(float4*)&hp[4] = *(const float4*)(hprev + 4);
#pragma unroll
    for (int i = 0; i < 8; i++) {
        const float* g4 = &sf[r * 68 + (uh * 8 + i) * 4];
        int j = j0 + i;
        float rg = sigmf(g4[0] + g_bcomb[j] + bhh[j]);
        float zg = sigmf(g4[1] + g_bcomb[HID + j] + bhh[HID + j]);
        float ng = tanhf(g4[2] + g_bcomb[2 * HID + j] + rg * (g4[3] + bhh[2 * HID + j]));
        hv[i] = (1.f - zg) * ng + zg * hp[i];
    }
    *(float4*)(hnew)     = *(float4*)&hv[0];
    *(float4*)(hnew + 4) = *(float4*)&hv[4];

    char* dst = g_Aimg + ((size_t)((t + 1) * 2 + mh) * 16 + (nt >> 2)) * 16384;
    uint32_t o = sw128((uint32_t)(r * 128 + (nt & 3) * 32 + uh * 16));
    *(uint4*)(dst + o) = cvt8h(hv);
    __syncthreads();
}

__device__ __forceinline__ void out_tile(uint32_t base, int tt, int ont, int omh,
                                         int tid, float* __restrict__ out,
                                         const float* __restrict__ bfc) {
    int wid = tid >> 5, lane = tid & 31;
    int wm = wid & 3, wn = wid >> 2;
    const char* Asrc = g_Aimg + (size_t)(tt * 2 + omh) * (16 * 16384);
    const char* Bsrc = g_Wfcimg + (size_t)ont * (16 * 32768);

    float acc[2][8][4];
#pragma unroll
    for (int a = 0; a < 2; a++)
#pragma unroll
        for (int b = 0; b < 8; b++)
#pragma unroll
            for (int cc = 0; cc < 4; cc++) acc[a][b][cc] = 0.f;

    {
        uint32_t d = base;
#pragma unroll
        for (int q = 0; q < 4; q++) cpa16(d + q * 4096 + tid * 16, Asrc + q * 4096 + tid * 16);
#pragma unroll
        for (int q = 0; q < 8; q++) cpa16(d + 16384 + q * 4096 + tid * 16, Bsrc + q * 4096 + tid * 16);
        CP_COMMIT();
    }

    for (int c = 0; c < 16; c++) {
        if (c < 15) {
            uint32_t d = base + ((c + 1) & 1) * OSTG;
#pragma unroll
            for (int q = 0; q < 4; q++)
                cpa16(d + q * 4096 + tid * 16, Asrc + (size_t)(c + 1) * 16384 + q * 4096 + tid * 16);
#pragma unroll
            for (int q = 0; q < 8; q++)
                cpa16(d + 16384 + q * 4096 + tid * 16, Bsrc + (size_t)(c + 1) * 32768 + q * 4096 + tid * 16);
            CP_COMMIT();
            CP_WAIT(1);
        } else {
            CP_WAIT(0);
        }
        __syncthreads();
        uint32_t sA = base + (c & 1) * OSTG;
        uint32_t sB = sA + 16384;
#pragma unroll
        for (int kk = 0; kk < 4; kk++) {
            uint32_t ah[2][4], bh[4][4], bl[4][4];
            int seg = kk * 32 + (lane >> 4) * 16;
#pragma unroll
            for (int mt = 0; mt < 2; mt++) {
                int r = wm * 32 + mt * 16 + (lane & 15);
                ldsm4(ah[mt], sA + sw128((uint32_t)(r * 128 + seg)));
            }
#pragma unroll
            for (int nq = 0; nq < 4; nq++) {
                int r = wn * 64 + nq * 16 + (lane & 15);
                uint32_t off = sw128((uint32_t)(r * 128 + seg));
                ldsm4(bh[nq], sB + off);
                ldsm4(bl[nq], sB + 16384 + off);
            }
#pragma unroll
            for (int mt = 0; mt < 2; mt++)
#pragma unroll
                for (int n8 = 0; n8 < 8; n8++) {
                    int nq = n8 >> 1, hf = n8 & 1;
                    mma16816h(acc[mt][n8], ah[mt], bh[nq][hf], bh[nq][hf + 2]);
                    mma16816h(acc[mt][n8], ah[mt], bl[nq][hf], bl[nq][hf + 2]);
                }
        }
        __syncthreads();
    }

    size_t row0 = (size_t)(tt - 1) * BATCH + omh * 128;
#pragma unroll
    for (int mt = 0; mt < 2; mt++)
#pragma unroll
        for (int n8 = 0; n8 < 8; n8++) {
            int rr = wm * 32 + mt * 16 + (lane >> 2);
            int cc = ont * 128 + wn * 64 + n8 * 8 + 2 * (lane & 3);
            float2 bv = *(const float2*)(bfc + cc);
            float2 v0 = make_float2(acc[mt][n8][0] + bv.x, acc[mt][n8][1] + bv.y);
            float2 v1 = make_float2(acc[mt][n8][2] + bv.x, acc[mt][n8][3] + bv.y);
            *(float2*)(out + (row0 + rr) * OUTD + cc)     = v0;
            *(float2*)(out + (row0 + rr + 8) * OUTD + cc) = v1;
        }
}

__global__ __launch_bounds__(256, 1) void uber(int T, const float* __restrict__ bhh,
                                               float* __restrict__ out,
                                               const float* __restrict__ bfc) {
    extern __shared__ char dsm[];
    __shared__ unsigned s_idx;
    uint32_t base = smem_u32(dsm);
    int bid = blockIdx.x, tid = threadIdx.x;

    if (bid < 128) {
        int nt = bid >> 1, mh = bid & 1;
        for (int t = 1; t < T; t++) {
            rec_step(base, dsm, t, nt, mh, tid, bhh);
            __threadfence();
            __syncthreads();
            if (tid == 0) {
                unsigned old = atomicAdd(&g_barm[mh], 1u);
                if (old == 64u * (unsigned)t - 1u) {
                    __threadfence();
                    g_stepm[mh] = (unsigned)(t + 1);
                }
                if (t + 1 < T) {
                    while (*((volatile unsigned*)&g_barm[mh]) < 64u * (unsigned)t) __nanosleep(64);
                }
            }
            __syncthreads();
            __threadfence();
        }
    }

    // out-tile work queue (all CTAs eventually)
    unsigned total = 12u * (unsigned)T;
    for (;;) {
        __syncthreads();
        if (tid == 0) s_idx = atomicAdd(&g_outq, 1u);
        __syncthreads();
        unsigned idx = s_idx;
        if (idx >= total) break;
        int tt = (int)(idx / 12u) + 1;
        int rem = (int)(idx % 12u);
        int ont = rem % 6, omh = rem / 6;
        if (tid == 0) {
            while (g_stepm[omh] < (unsigned)tt) __nanosleep(128);
        }
        __syncthreads();
        __threadfence();
        out_tile(base, tt, ont, omh, tid, out, bfc);
    }
}

// ===========================================================================
extern "C" void kernel_launch(void* const* d_in, const int* in_sizes, int n_in,
                              void* d_out, int out_size) {
    const float* src    = (const float*)d_in[0];
    const float* hidden = (const float*)d_in[2];
    const float* W_ih   = (const float*)d_in[3];
    const float* W_hh   = (const float*)d_in[4];
    const float* b_ih   = (const float*)d_in[5];
    const float* b_hh   = (const float*)d_in[6];
    const float* W_fc   = (const float*)d_in[7];
    const float* b_fc   = (const float*)d_in[8];
    float* out = (float*)d_out;

    int T = out_size / (BATCH * OUTD);
    if (T > TMAX) T = TMAX;
    if (T < 1) T = 1;

    float *pH, *pWihf, *pWhhf, *pWc, *pbc;
    cudaGetSymbolAddress((void**)&pH, g_H);
    cudaGetSymbolAddress((void**)&pWihf, g_Wih_f);
    cudaGetSymbolAddress((void**)&pWhhf, g_Whh_f);
    cudaGetSymbolAddress((void**)&pWc, g_Wc);
    cudaGetSymbolAddress((void**)&pbc, g_bcomb);

    cudaFuncSetAttribute(uber, cudaFuncAttributeMaxDynamicSharedMemorySize, UBER_DYN);

    // --- precompute ---
    init_sync<<<1, 1>>>();
    pack_w<<<dim3(OUTD / 32, NJB, 3), 256>>>(pWihf, W_ih, OUTD);
    pack_w<<<dim3(HID / 32, NJB, 3), 256>>>(pWhhf, W_hh, HID);
    gemm_nn<<<dim3(HID / 64, (3 * HID) / 128), 256>>>(W_ih, W_fc, nullptr, pWc,
                                                      3 * HID, HID, OUTD);
    bcomb_k<<<(3 * HID) / 8, 256>>>(W_ih, b_fc, b_ih, pbc);
    copy_f<<<(BATCH * HID / 4 + 255) / 256, 256>>>(pH, hidden, BATCH * HID / 4);
    pack_wimg<<<dim3(64, 16), 256>>>(pWc, W_hh);
    pack_wfcimg<<<dim3(6, 16), 256>>>(W_fc);

    // --- step 0 (SIMT fp32, K=768 input path) ---
    gru_step<<<dim3(NJB, BATCH / 64), 256>>>(src, OUTD, pWihf, b_ih,
                                             pH, pWhhf, b_hh,
                                             pH + (size_t)BATCH * HID);
    h2img<<<dim3(2, 16), 256>>>();

    // --- über-kernel: recurrence + work-stealing output projection ---
    uber<<<148, 256, UBER_DYN>>>(T, b_hh, out, b_fc);
}

// round 9
// speedup vs baseline: 2.4479x; 1.5467x over previous
#include <cuda_runtime.h>
#include <cuda_fp16.h>
#include <math.h>
#include <stdint.h>

#define HID   1024
#define OUTD  768
#define BATCH 256
#define TMAX  256
#define NJB   (HID / 32)

// ===========================================================================
// helpers
// ===========================================================================
__device__ __forceinline__ uint32_t smem_u32(const void* p) {
    uint32_t a;
    asm("{ .reg .u64 t; cvta.to.shared.u64 t, %1; cvt.u32.u64 %0, t; }" : "=r"(a) : "l"(p));
    return a;
}
__device__ __host__ __forceinline__ uint32_t sw128(uint32_t off) {
    return off ^ ((off >> 3) & 0x70);
}
__device__ __forceinline__ void cpa16(uint32_t dst, const void* src) {
    asm volatile("cp.async.cg.shared.global [%0], [%1], 16;" :: "r"(dst), "l"(src));
}
#define CP_COMMIT() asm volatile("cp.async.commit_group;" ::: "memory")
#define CP_WAIT(n)  asm volatile("cp.async.wait_group %0;" :: "n"(n) : "memory")

__device__ __forceinline__ void ldsm4(uint32_t (&r)[4], uint32_t addr) {
    asm volatile("ldmatrix.sync.aligned.m8n8.x4.shared.b16 {%0,%1,%2,%3}, [%4];"
        : "=r"(r[0]), "=r"(r[1]), "=r"(r[2]), "=r"(r[3]) : "r"(addr));
}
__device__ __forceinline__ void mma16816h(float (&d)[4], const uint32_t (&a)[4],
                                          uint32_t b0, uint32_t b1) {
    asm volatile("mma.sync.aligned.m16n8k16.row.col.f32.f16.f16.f32 "
        "{%0,%1,%2,%3}, {%4,%5,%6,%7}, {%8,%9}, {%0,%1,%2,%3};"
        : "+f"(d[0]), "+f"(d[1]), "+f"(d[2]), "+f"(d[3])
        : "r"(a[0]), "r"(a[1]), "r"(a[2]), "r"(a[3]), "r"(b0), "r"(b1));
}

// ===========================================================================
// device scratch
// ===========================================================================
__device__ float g_H[(TMAX + 1) * BATCH * HID];
__device__ float g_Wih_f[NJB * OUTD * 3 * 32];
__device__ float g_Whh_f[NJB * HID * 3 * 32];
__device__ float g_Wc[3 * HID * HID];
__device__ float g_bcomb[3 * HID];
__device__ unsigned g_barm[2];
__device__ volatile unsigned g_stepm[2];
__device__ unsigned g_outq;
// fp16 SW128 tile images
__device__ __align__(1024) char g_Aimg[(size_t)(TMAX + 1) * 2 * 16 * 16384]; // [t][mh][kc] 128x64 fp16
__device__ __align__(1024) char g_Wimg[(size_t)64 * 16 * 8192];              // fused single-fp16 [nt][kc]
__device__ __align__(1024) char g_Wfcimg[(size_t)6 * 16 * 32768];            // [nt][kc]{hi16K,lo16K}

// ===========================================================================
// fp32 SIMT pieces (step 0 + W_comb precompute)
// ===========================================================================
__device__ __forceinline__ unsigned long long dup2(float x) {
    unsigned long long r;
    asm("mov.b64 %0, {%1, %1};" : "=l"(r) : "f"(x));
    return r;
}
__device__ __forceinline__ void fmax2(unsigned long long& d, unsigned long long a,
                                      unsigned long long b) {
    asm("fma.rn.f32x2 %0, %1, %2, %0;" : "+l"(d) : "l"(a), "l"(b));
}
union F4U { float4 f; unsigned long long u[2]; };
union U2F { unsigned long long u; float2 f; };
__device__ __forceinline__ float sigmf(float x) { return 1.0f / (1.0f + __expf(-x)); }

__global__ __launch_bounds__(256) void pack_w(float* __restrict__ dst,
                                              const float* __restrict__ src, int Ks) {
    __shared__ float sm[32][33];
    int k0 = blockIdx.x * 32, jb = blockIdx.y, g = blockIdx.z, t = threadIdx.x;
    int jl = t >> 3, kq = t & 7;
    float4 v = *(const float4*)(src + (size_t)(g * HID + jb * 32 + jl) * Ks + k0 + kq * 4);
    sm[jl][kq * 4 + 0] = v.x; sm[jl][kq * 4 + 1] = v.y;
    sm[jl][kq * 4 + 2] = v.z; sm[jl][kq * 4 + 3] = v.w;
    __syncthreads();
    int ji = t & 31, kk0 = t >> 5;
#pragma unroll
    for (int r = 0; r < 4; r++) {
        int kk = kk0 + r * 8;
        dst[(((size_t)jb * Ks + k0 + kk) * 3 + g) * 32 + ji] = sm[ji][kk];
    }
}

__global__ __launch_bounds__(256) void bcomb_k(const float* __restrict__ Wih,
                                               const float* __restrict__ bfc,
                                               const float* __restrict__ bih,
                                               float* __restrict__ out) {
    int j = blockIdx.x * 8 + (threadIdx.x >> 5);
    int lane = threadIdx.x & 31;
    float s = 0.f;
    for (int o = lane; o < OUTD; o += 32) s += Wih[(size_t)j * OUTD + o] * bfc[o];
#pragma unroll
    for (int off = 16; off; off >>= 1) s += __shfl_xor_sync(0xffffffffu, s, off);
    if (lane == 0) out[j] = s + bih[j];
}

__global__ __launch_bounds__(256) void copy_f(float* __restrict__ dst,
                                              const float* __restrict__ src, int n4) {
    int i = blockIdx.x * 256 + threadIdx.x;
    if (i < n4) ((float4*)dst)[i] = ((const float4*)src)[i];
}

__global__ void init_sync() {
    g_barm[0] = 0; g_barm[1] = 0;
    g_stepm[0] = 1; g_stepm[1] = 1;
    g_outq = 0;
}

__global__ __launch_bounds__(256) void gemm_nn(const float* __restrict__ A,
                                               const float* __restrict__ B,
                                               const float* __restrict__ bias,
                                               float* __restrict__ C,
                                               int M, int N, int K) {
    __shared__ float2 sA[32][66];
    __shared__ float  sB[32][64];
    int n0 = blockIdx.x * 64, m0 = blockIdx.y * 128, t = threadIdx.x;
    int tn = t & 15, tm = t >> 4;
    unsigned long long acc[4][4] = {};
    float4 ast[4], bst[2];
#pragma unroll
    for (int r = 0; r < 4; r++) {
        int idx = t + 256 * r, m = idx >> 3, kf = idx & 7;
        ast[r] = *(const float4*)(A + (size_t)(m0 + m) * K + kf * 4);
    }
#pragma unroll
    for (int r = 0; r < 2; r++) {
        int idx = t + 256 * r, kk = idx >> 4, nf = idx & 15;
        bst[r] = *(const float4*)(B + (size_t)kk * N + n0 + nf * 4);
    }
    int nch = K >> 5;
    for (int ch = 0; ch < nch; ch++) {
        float* sp = (float*)&sA[0][0];
#pragma unroll
        for (int r = 0; r < 4; r++) {
            int idx = t + 256 * r, m = idx >> 3, kf = idx & 7;
            sp[(kf * 4 + 0) * 132 + m] = ast[r].x; sp[(kf * 4 + 1) * 132 + m] = ast[r].y;
            sp[(kf * 4 + 2) * 132 + m] = ast[r].z; sp[(kf * 4 + 3) * 132 + m] = ast[r].w;
        }
#pragma unroll
        for (int r = 0; r < 2; r++) {
            int idx = t + 256 * r, kk = idx >> 4, nf = idx & 15;
            *(float4*)&sB[kk][nf * 4] = bst[r];
        }
        __syncthreads();
        if (ch + 1 < nch) {
            int k0 = (ch + 1) * 32;
#pragma unroll
            for (int r = 0; r < 4; r++) {
                int idx = t + 256 * r, m = idx >> 3, kf = idx & 7;
                ast[r] = *(const float4*)(A + (size_t)(m0 + m) * K + k0 + kf * 4);
            }
#pragma unroll
            for (int r = 0; r < 2; r++) {
                int idx = t + 256 * r, kk = idx >> 4, nf = idx & 15;
                bst[r] = *(const float4*)(B + (size_t)(k0 + kk) * N + n0 + nf * 4);
            }
        }
#pragma unroll 8
        for (int k = 0; k < 32; k++) {
            F4U a0, a1, bv;
            a0.f = *(const float4*)&sA[k][tm * 4];
            a1.f = *(const float4*)&sA[k][tm * 4 + 2];
            bv.f = *(const float4*)&sB[k][tn * 4];
            unsigned long long d0 = dup2(bv.f.x), d1 = dup2(bv.f.y),
                               d2 = dup2(bv.f.z), d3 = dup2(bv.f.w);
            fmax2(acc[0][0], a0.u[0], d0); fmax2(acc[0][1], a0.u[1], d0);
            fmax2(acc[0][2], a1.u[0], d0); fmax2(acc[0][3], a1.u[1], d0);
            fmax2(acc[1][0], a0.u[0], d1); fmax2(acc[1][1], a0.u[1], d1);
            fmax2(acc[1][2], a1.u[0], d1); fmax2(acc[1][3], a1.u[1], d1);
            fmax2(acc[2][0], a0.u[0], d2); fmax2(acc[2][1], a0.u[1], d2);
            fmax2(acc[2][2], a1.u[0], d2); fmax2(acc[2][3], a1.u[1], d2);
            fmax2(acc[3][0], a0.u[0], d3); fmax2(acc[3][1], a0.u[1], d3);
            fmax2(acc[3][2], a1.u[0], d3); fmax2(acc[3][3], a1.u[1], d3);
        }
        __syncthreads();
    }
#pragma unroll
    for (int ni = 0; ni < 4; ni++) {
        int n = n0 + tn * 4 + ni;
        float bv = bias ? bias[n] : 0.f;
#pragma unroll
        for (int p = 0; p < 4; p++) {
            U2F v; v.u = acc[ni][p];
            int m = m0 + tm * 8 + p * 2;
            C[(size_t)m * N + n] = v.f.x + bv;
            C[(size_t)(m + 1) * N + n] = v.f.y + bv;
        }
    }
}

// SIMT GRU step (step 0 only)
__device__ __forceinline__ void gru_phase(unsigned long long (&acc)[3][4],
                                          const float* __restrict__ src, int Kd,
                                          const float* __restrict__ Wf,
                                          int jb, int b0, int t, int tx, int ty,
                                          float* sW, float2 (*sH)[34]) {
    const float* Wp = Wf + (size_t)jb * Kd * 96;
    int nch = Kd >> 5;
    float4 wst0, wst1, wst2, hst0, hst1;
    {
        const float4* wp4 = (const float4*)Wp;
        wst0 = wp4[t]; wst1 = wp4[t + 256]; wst2 = wp4[t + 512];
        int i0 = t, i1 = t + 256;
        hst0 = *(const float4*)(src + (size_t)(b0 + (i0 >> 3)) * Kd + ((i0 & 7) << 2));
        hst1 = *(const float4*)(src + (size_t)(b0 + (i1 >> 3)) * Kd + ((i1 & 7) << 2));
    }
    for (int ch = 0; ch < nch; ch++) {
        ((float4*)sW)[t] = wst0; ((float4*)sW)[t + 256] = wst1; ((float4*)sW)[t + 512] = wst2;
        float* sp = (float*)&sH[0][0];
        {
            int m = t >> 3, kf = t & 7;
            sp[(kf * 4 + 0) * 68 + m] = hst0.x; sp[(kf * 4 + 1) * 68 + m] = hst0.y;
            sp[(kf * 4 + 2) * 68 + m] = hst0.z; sp[(kf * 4 + 3) * 68 + m] = hst0.w;
            int i1 = t + 256; m = i1 >> 3; kf = i1 & 7;
            sp[(kf * 4 + 0) * 68 + m] = hst1.x; sp[(kf * 4 + 1) * 68 + m] = hst1.y;
            sp[(kf * 4 + 2) * 68 + m] = hst1.z; sp[(kf * 4 + 3) * 68 + m] = hst1.w;
        }
        __syncthreads();
        if (ch + 1 < nch) {
            int k0 = (ch + 1) * 32;
            const float4* wp4 = (const float4*)(Wp + (size_t)k0 * 96);
            wst0 = wp4[t]; wst1 = wp4[t + 256]; wst2 = wp4[t + 512];
            int i0 = t, i1 = t + 256;
            hst0 = *(const float4*)(src + (size_t)(b0 + (i0 >> 3)) * Kd + k0 + ((i0 & 7) << 2));
            hst1 = *(const float4*)(src + (size_t)(b0 + (i1 >> 3)) * Kd + k0 + ((i1 & 7) << 2));
        }
#pragma unroll 8
        for (int k = 0; k < 32; k++) {
            F4U a0, a1;
            a0.f = *(const float4*)&sH[k][ty * 4];
            a1.f = *(const float4*)&sH[k][ty * 4 + 2];
            float w0 = sW[k * 96 + tx], w1 = sW[k * 96 + 32 + tx], w2 = sW[k * 96 + 64 + tx];
            unsigned long long d0 = dup2(w0), d1 = dup2(w1), d2 = dup2(w2);
            fmax2(acc[0][0], a0.u[0], d0); fmax2(acc[0][1], a0.u[1], d0);
            fmax2(acc[0][2], a1.u[0], d0); fmax2(acc[0][3], a1.u[1], d0);
            fmax2(acc[1][0], a0.u[0], d1); fmax2(acc[1][1], a0.u[1], d1);
            fmax2(acc[1][2], a1.u[0], d1); fmax2(acc[1][3], a1.u[1], d1);
            fmax2(acc[2][0], a0.u[0], d2); fmax2(acc[2][1], a0.u[1], d2);
            fmax2(acc[2][2], a1.u[0], d2); fmax2(acc[2][3], a1.u[1], d2);
        }
        __syncthreads();
    }
}

__global__ __launch_bounds__(256) void gru_step(const float* __restrict__ inp, int Ki,
                                                const float* __restrict__ Wi,
                                                const float* __restrict__ bi,
                                                const float* __restrict__ hin,
                                                const float* __restrict__ Wh,
                                                const float* __restrict__ bh,
                                                float* __restrict__ hout) {
    __shared__ float  sW[32 * 96];
    __shared__ float2 sH[32][34];
    int jb = blockIdx.x, b0 = blockIdx.y * 64, t = threadIdx.x;
    int tx = t & 31, ty = t >> 5;
    unsigned long long acci[3][4] = {};
    unsigned long long acch[3][4] = {};
    gru_phase(acci, inp, Ki, Wi, jb, b0, t, tx, ty, sW, sH);
    gru_phase(acch, hin, HID, Wh, jb, b0, t, tx, ty, sW, sH);
    int j = jb * 32 + tx;
    float bir = bi[j], bhr = bh[j];
    float biz = bi[HID + j], bhz = bh[HID + j];
    float bin_ = bi[2 * HID + j], bhn = bh[2 * HID + j];
#pragma unroll
    for (int p = 0; p < 4; p++) {
        U2F ir, iz, in_, hr, hz, hn;
        ir.u = acci[0][p]; iz.u = acci[1][p]; in_.u = acci[2][p];
        hr.u = acch[0][p]; hz.u = acch[1][p]; hn.u = acch[2][p];
        int b = b0 + ty * 8 + p * 2;
        float r0 = sigmf(ir.f.x + bir + hr.f.x + bhr);
        float z0 = sigmf(iz.f.x + biz + hz.f.x + bhz);
        float n0 = tanhf(in_.f.x + bin_ + r0 * (hn.f.x + bhn));
        float hp0 = hin[(size_t)b * HID + j];
        hout[(size_t)b * HID + j] = (1.f - z0) * n0 + z0 * hp0;
        float r1 = sigmf(ir.f.y + bir + hr.f.y + bhr);
        float z1 = sigmf(iz.f.y + biz + hz.f.y + bhz);
        float n1 = tanhf(in_.f.y + bin_ + r1 * (hn.f.y + bhn));
        float hp1 = hin[(size_t)(b + 1) * HID + j];
        hout[(size_t)(b + 1) * HID + j] = (1.f - z1) * n1 + z1 * hp1;
    }
}

// ===========================================================================
// fp16 split + packers
// ===========================================================================
union BPK { unsigned short s[8]; uint4 v; };
__device__ __forceinline__ void split8h(const float* v, uint4& hi, uint4& lo) {
    BPK ph, pl;
#pragma unroll
    for (int i = 0; i < 8; i++) {
        __half a = __float2half(v[i]);
        float r = v[i] - __half2float(a);
        __half b = __float2half(r);
        ph.s[i] = *(unsigned short*)&a;
        pl.s[i] = *(unsigned short*)&b;
    }
    hi = ph.v; lo = pl.v;
}
__device__ __forceinline__ uint4 cvt8h(const float* v) {
    BPK p;
#pragma unroll
    for (int i = 0; i < 8; i++) {
        __half a = __float2half(v[i]);
        p.s[i] = *(unsigned short*)&a;
    }
    return p.v;
}

// Gate-fused W image (single fp16): nt(64) x kc(16): 64 rows x 64 k (8KB blocks)
// row = jt*4 + c;  c=0: Wc_r+Whh_r, c=1: Wc_z+Whh_z, c=2: Wc_n, c=3: Whh_n
__global__ __launch_bounds__(256) void pack_wimg(const float* __restrict__ Wc,
                                                 const float* __restrict__ Whh) {
    int nt = blockIdx.x, kc = blockIdx.y, tid = threadIdx.x;
    char* dst = g_Wimg + ((size_t)nt * 16 + kc) * 8192;
    for (int u = tid; u < 512; u += 256) {
        int r = u >> 3, unit = u & 7;
        int jt = r >> 2, c = r & 3;
        int j = nt * 16 + jt;
        float v[8];
        if (c < 2) {
            const float* s1 = Wc  + (size_t)(c * HID + j) * HID + kc * 64 + unit * 8;
            const float* s2 = Whh + (size_t)(c * HID + j) * HID + kc * 64 + unit * 8;
            float4 a0 = *(const float4*)s1, a1 = *(const float4*)(s1 + 4);
            float4 b0 = *(const float4*)s2, b1 = *(const float4*)(s2 + 4);
            v[0] = a0.x + b0.x; v[1] = a0.y + b0.y; v[2] = a0.z + b0.z; v[3] = a0.w + b0.w;
            v[4] = a1.x + b1.x; v[5] = a1.y + b1.y; v[6] = a1.z + b1.z; v[7] = a1.w + b1.w;
        } else {
            const float* s1 = (c == 2 ? Wc : Whh) + (size_t)(2 * HID + j) * HID + kc * 64 + unit * 8;
            *(float4*)&v[0] = *(const float4*)s1;
            *(float4*)&v[4] = *(const float4*)(s1 + 4);
        }
        uint32_t o = sw128((uint32_t)(r * 128 + unit * 16));
        *(uint4*)(dst + o) = cvt8h(v);
    }
}

// W_fc images (fp16 hi/lo): nt(6) x kc(16): 128 rows x 64 k
__global__ __launch_bounds__(256) void pack_wfcimg(const float* __restrict__ Wfc) {
    int nt = blockIdx.x, kc = blockIdx.y, tid = threadIdx.x;
    char* dst = g_Wfcimg + ((size_t)nt * 16 + kc) * 32768;
    for (int u = tid; u < 1024; u += 256) {
        int r = u >> 3, unit = u & 7;
        const float* srcrow = Wfc + (size_t)(nt * 128 + r) * HID + kc * 64 + unit * 8;
        float v[8];
        *(float4*)&v[0] = *(const float4*)srcrow;
        *(float4*)&v[4] = *(const float4*)(srcrow + 4);
        uint4 hi, lo; split8h(v, hi, lo);
        uint32_t o = sw128((uint32_t)(r * 128 + unit * 16));
        *(uint4*)(dst + o) = hi;
        *(uint4*)(dst + 16384 + o) = lo;
    }
}

// h_1 -> fp16 A image for t=1
__global__ __launch_bounds__(256) void h2img() {
    int mh = blockIdx.x, kc = blockIdx.y, tid = threadIdx.x;
    char* dst = g_Aimg + ((size_t)(1 * 2 + mh) * 16 + kc) * 16384;
    for (int u = tid; u < 1024; u += 256) {
        int r = u >> 3, unit = u & 7;
        const float* hp = g_H + ((size_t)1 * BATCH + mh * 128 + r) * HID + kc * 64 + unit * 8;
        float v[8];
        *(float4*)&v[0] = *(const float4*)hp;
        *(float4*)&v[4] = *(const float4*)(hp + 4);
        uint32_t o = sw128((uint32_t)(r * 128 + unit * 16));
        *(uint4*)(dst + o) = cvt8h(v);
    }
}

// ===========================================================================
// über-kernel: 148 CTAs. bid<128: persistent recurrence with W resident in
// SMEM (128KB) + 3-stage A pipeline (K=128 chunks); then join out queue.
// bid>=128: out-tile workers from the start.
// ===========================================================================
#define WRES 131072      // resident W: 64 rows x 1024 k fp16
#define RSTG 32768       // A stage: 128 rows x 128 k fp16
#define OSTG 98304       // out stage: A 32K + Bfc(hi/lo) 64K
#define UBER_DYN 229376  // 224 KB

__device__ __forceinline__ void rec_step(uint32_t base, char* dsm, int t, int nt, int mh,
                                         int tid, const float* __restrict__ rb,
                                         const float* __restrict__ zb,
                                         const float* __restrict__ nb,
                                         const float* __restrict__ nh) {
    int wid = tid >> 5, lane = tid & 31;
    int wm = wid & 3, wn = wid >> 2;
    const char* Asrc = g_Aimg + (size_t)(t * 2 + mh) * (16 * 16384);
    uint32_t aBase = base + WRES;

    float acc[2][4][4];
#pragma unroll
    for (int a = 0; a < 2; a++)
#pragma unroll
        for (int b = 0; b < 4; b++)
#pragma unroll
            for (int cc = 0; cc < 4; cc++) acc[a][b][cc] = 0.f;

#pragma unroll
    for (int pc = 0; pc < 2; pc++) {
        uint32_t d = aBase + pc * RSTG;
#pragma unroll
        for (int q = 0; q < 8; q++)
            cpa16(d + q * 4096 + tid * 16, Asrc + (size_t)pc * 32768 + q * 4096 + tid * 16);
        CP_COMMIT();
    }

    for (int c = 0; c < 8; c++) {
        if (c == 7) { CP_WAIT(0); } else { CP_WAIT(1); }
        __syncthreads();
        if (c + 2 < 8) {
            uint32_t d = aBase + ((c + 2) % 3) * RSTG;
#pragma unroll
            for (int q = 0; q < 8; q++)
                cpa16(d + q * 4096 + tid * 16, Asrc + (size_t)(c + 2) * 32768 + q * 4096 + tid * 16);
            CP_COMMIT();
        }
        uint32_t sA = aBase + (c % 3) * RSTG;
        uint32_t sW = base + c * 16384;  // 2 kc-blocks of 8KB within resident W
#pragma unroll
        for (int kk = 0; kk < 8; kk++) {
            uint32_t ah[2][4], bh[2][4];
            int blk = kk >> 2;
            int seg = (kk & 3) * 32 + (lane >> 4) * 16;
#pragma unroll
            for (int mt = 0; mt < 2; mt++) {
                int r = wm * 32 + mt * 16 + (lane & 15);
                ldsm4(ah[mt], sA + blk * 16384 + sw128((uint32_t)(r * 128 + seg)));
            }
#pragma unroll
            for (int nq = 0; nq < 2; nq++) {
                int r = wn * 32 + nq * 16 + (lane & 15);
                ldsm4(bh[nq], sW + blk * 8192 + sw128((uint32_t)(r * 128 + seg)));
            }
#pragma unroll
            for (int mt = 0; mt < 2; mt++)
#pragma unroll
                for (int n8 = 0; n8 < 4; n8++) {
                    int nq = n8 >> 1, hf = n8 & 1;
                    mma16816h(acc[mt][n8], ah[mt], bh[nq][hf], bh[nq][hf + 2]);
                }
        }
    }

    // epilogue: accs -> smem (in A-stage region), then gates
    __syncthreads();
    float* sf = (float*)(dsm + WRES);
#pragma unroll
    for (int mt = 0; mt < 2; mt++)
#pragma unroll
        for (int n8 = 0; n8 < 4; n8++) {
            int r0 = wm * 32 + mt * 16 + (lane >> 2);
            int c0 = wn * 32 + n8 * 8 + 2 * (lane & 3);
            *(float2*)&sf[r0 * 68 + c0]       = make_float2(acc[mt][n8][0], acc[mt][n8][1]);
            *(float2*)&sf[(r0 + 8) * 68 + c0] = make_float2(acc[mt][n8][2], acc[mt][n8][3]);
        }
    __syncthreads();

    int r = tid >> 1, uh = tid & 1;
    int b = mh * 128 + r;
    int j0 = nt * 16 + uh * 8;
    const float* hprev = g_H + ((size_t)t * BATCH + b) * HID + j0;
    float* hnew = g_H + ((size_t)(t + 1) * BATCH + b) * HID + j0;
    float hp[8], hv[8];
    *(float4*)&hp[0] = *(const float4*)(hprev);
    *(float4*)&hp[4] = *(const float4*)(hprev + 4);
#pragma unroll
    for (int i = 0; i < 8; i++) {
        const float* g4 = &sf[r * 68 + (uh * 8 + i) * 4];
        float rg = sigmf(g4[0] + rb[i]);
        float zg = sigmf(g4[1] + zb[i]);
        float ng = tanhf(g4[2] + nb[i] + rg * (g4[3] + nh[i]));
        hv[i] = (1.f - zg) * ng + zg * hp[i];
    }
    *(float4*)(hnew)     = *(float4*)&hv[0];
    *(float4*)(hnew + 4) = *(float4*)&hv[4];

    char* dst = g_Aimg + ((size_t)((t + 1) * 2 + mh) * 16 + (nt >> 2)) * 16384;
    uint32_t o = sw128((uint32_t)(r * 128 + (nt & 3) * 32 + uh * 16));
    *(uint4*)(dst + o) = cvt8h(hv);
    __syncthreads();
}

__device__ __forceinline__ void out_tile(uint32_t base, int tt, int ont, int omh,
                                         int tid, float* __restrict__ out,
                                         const float* __restrict__ bfc) {
    int wid = tid >> 5, lane = tid & 31;
    int wm = wid & 1, wn = wid >> 1;   // 2 m-blocks x 4 n-blocks
    const char* Asrc = g_Aimg + (size_t)(tt * 2 + omh) * (16 * 16384);
    const char* Bsrc = g_Wfcimg + (size_t)ont * (16 * 32768);

    float acc[4][4][4];
#pragma unroll
    for (int a = 0; a < 4; a++)
#pragma unroll
        for (int b = 0; b < 4; b++)
#pragma unroll
            for (int cc = 0; cc < 4; cc++) acc[a][b][cc] = 0.f;

    {
        uint32_t d = base;
#pragma unroll
        for (int q = 0; q < 8; q++) cpa16(d + q * 4096 + tid * 16, Asrc + q * 4096 + tid * 16);
#pragma unroll
        for (int q = 0; q < 16; q++) cpa16(d + 32768 + q * 4096 + tid * 16, Bsrc + q * 4096 + tid * 16);
        CP_COMMIT();
    }

    for (int c = 0; c < 8; c++) {
        if (c < 7) {
            uint32_t d = base + ((c + 1) & 1) * OSTG;
#pragma unroll
            for (int q = 0; q < 8; q++)
                cpa16(d + q * 4096 + tid * 16, Asrc + (size_t)(c + 1) * 32768 + q * 4096 + tid * 16);
#pragma unroll
            for (int q = 0; q < 16; q++)
                cpa16(d + 32768 + q * 4096 + tid * 16, Bsrc + (size_t)(c + 1) * 65536 + q * 4096 + tid * 16);
            CP_COMMIT();
            CP_WAIT(1);
        } else {
            CP_WAIT(0);
        }
        __syncthreads();
        uint32_t sA = base + (c & 1) * OSTG;
        uint32_t sB = sA + 32768;
#pragma unroll
        for (int kk = 0; kk < 8; kk++) {
            uint32_t ah[4][4], bh[2][4], bl[2][4];
            int blk = kk >> 2;
            int seg = (kk & 3) * 32 + (lane >> 4) * 16;
#pragma unroll
            for (int mt = 0; mt < 4; mt++) {
                int r = wm * 64 + mt * 16 + (lane & 15);
                ldsm4(ah[mt], sA + blk * 16384 + sw128((uint32_t)(r * 128 + seg)));
            }
#pragma unroll
            for (int nq = 0; nq < 2; nq++) {
                int r = wn * 32 + nq * 16 + (lane & 15);
                uint32_t off = blk * 32768 + sw128((uint32_t)(r * 128 + seg));
                ldsm4(bh[nq], sB + off);
                ldsm4(bl[nq], sB + 16384 + off);
            }
#pragma unroll
            for (int mt = 0; mt < 4; mt++)
#pragma unroll
                for (int n8 = 0; n8 < 4; n8++) {
                    int nq = n8 >> 1, hf = n8 & 1;
                    mma16816h(acc[mt][n8], ah[mt], bh[nq][hf], bh[nq][hf + 2]);
                    mma16816h(acc[mt][n8], ah[mt], bl[nq][hf], bl[nq][hf + 2]);
                }
        }
        __syncthreads();
    }

    size_t row0 = (size_t)(tt - 1) * BATCH + omh * 128;
#pragma unroll
    for (int mt = 0; mt < 4; mt++)
#pragma unroll
        for (int n8 = 0; n8 < 4; n8++) {
            int rr = wm * 64 + mt * 16 + (lane >> 2);
            int cc = ont * 128 + wn * 32 + n8 * 8 + 2 * (lane & 3);
            float2 bv = *(const float2*)(bfc + cc);
            float2 v0 = make_float2(acc[mt][n8][0] + bv.x, acc[mt][n8][1] + bv.y);
            float2 v1 = make_float2(acc[mt][n8][2] + bv.x, acc[mt][n8][3] + bv.y);
            *(float2*)(out + (row0 + rr) * OUTD + cc)     = v0;
            *(float2*)(out + (row0 + rr + 8) * OUTD + cc) = v1;
        }
}

__global__ __launch_bounds__(256, 1) void uber(int T, const float* __restrict__ bhh,
                                               float* __restrict__ out,
                                               const float* __restrict__ bfc) {
    extern __shared__ char dsm[];
    __shared__ unsigned s_idx;
    uint32_t base = smem_u32(dsm);
    int bid = blockIdx.x, tid = threadIdx.x;

    if (bid < 128 && T > 1) {
        int nt = bid >> 1, mh = bid & 1;

        // load W resident (128 KB, once)
        {
            const char* Wsrc = g_Wimg + (size_t)nt * (16 * 8192);
#pragma unroll
            for (int q = 0; q < 32; q++)
                cpa16(base + q * 4096 + tid * 16, Wsrc + q * 4096 + tid * 16);
            CP_COMMIT(); CP_WAIT(0);
            __syncthreads();
        }

        // hoist per-thread gate biases
        float rb[8], zb[8], nb[8], nh[8];
        {
            int uh = tid & 1;
            int j0 = nt * 16 + uh * 8;
#pragma unroll
            for (int i = 0; i < 8; i++) {
                int j = j0 + i;
                rb[i] = g_bcomb[j] + bhh[j];
                zb[i] = g_bcomb[HID + j] + bhh[HID + j];
                nb[i] = g_bcomb[2 * HID + j];
                nh[i] = bhh[2 * HID + j];
            }
        }

        for (int t = 1; t < T; t++) {
            rec_step(base, dsm, t, nt, mh, tid, rb, zb, nb, nh);
            __threadfence();
            __syncthreads();
            if (tid == 0) {
                unsigned old = atomicAdd(&g_barm[mh], 1u);
                if (old == 64u * (unsigned)t - 1u) {
                    __threadfence();
                    g_stepm[mh] = (unsigned)(t + 1);
                }
                if (t + 1 < T) {
                    while (*((volatile unsigned*)&g_barm[mh]) < 64u * (unsigned)t) __nanosleep(32);
                }
            }
            __syncthreads();
            __threadfence();
        }
    }

    // out-tile work queue (all CTAs eventually)
    unsigned total = 12u * (unsigned)T;
    for (;;) {
        __syncthreads();
        if (tid == 0) s_idx = atomicAdd(&g_outq, 1u);
        __syncthreads();
        unsigned idx = s_idx;
        if (idx >= total) break;
        int tt = (int)(idx / 12u) + 1;
        int rem = (int)(idx % 12u);
        int ont = rem % 6, omh = rem / 6;
        if (tid == 0) {
            while (g_stepm[omh] < (unsigned)tt) __nanosleep(128);
        }
        __syncthreads();
        __threadfence();
        out_tile(base, tt, ont, omh, tid, out, bfc);
    }
}

// ===========================================================================
extern "C" void kernel_launch(void* const* d_in, const int* in_sizes, int n_in,
                              void* d_out, int out_size) {
    const float* src    = (const float*)d_in[0];
    const float* hidden = (const float*)d_in[2];
    const float* W_ih   = (const float*)d_in[3];
    const float* W_hh   = (const float*)d_in[4];
    const float* b_ih   = (const float*)d_in[5];
    const float* b_hh   = (const float*)d_in[6];
    const float* W_fc   = (const float*)d_in[7];
    const float* b_fc   = (const float*)d_in[8];
    float* out = (float*)d_out;

    int T = out_size / (BATCH * OUTD);
    if (T > TMAX) T = TMAX;
    if (T < 1) T = 1;

    float *pH, *pWihf, *pWhhf, *pWc, *pbc;
    cudaGetSymbolAddress((void**)&pH, g_H);
    cudaGetSymbolAddress((void**)&pWihf, g_Wih_f);
    cudaGetSymbolAddress((void**)&pWhhf, g_Whh_f);
    cudaGetSymbolAddress((void**)&pWc, g_Wc);
    cudaGetSymbolAddress((void**)&pbc, g_bcomb);

    cudaFuncSetAttribute(uber, cudaFuncAttributeMaxDynamicSharedMemorySize, UBER_DYN);

    // --- precompute ---
    init_sync<<<1, 1>>>();
    pack_w<<<dim3(OUTD / 32, NJB, 3), 256>>>(pWihf, W_ih, OUTD);
    pack_w<<<dim3(HID / 32, NJB, 3), 256>>>(pWhhf, W_hh, HID);
    gemm_nn<<<dim3(HID / 64, (3 * HID) / 128), 256>>>(W_ih, W_fc, nullptr, pWc,
                                                      3 * HID, HID, OUTD);
    bcomb_k<<<(3 * HID) / 8, 256>>>(W_ih, b_fc, b_ih, pbc);
    copy_f<<<(BATCH * HID / 4 + 255) / 256, 256>>>(pH, hidden, BATCH * HID / 4);
    pack_wimg<<<dim3(64, 16), 256>>>(pWc, W_hh);
    pack_wfcimg<<<dim3(6, 16), 256>>>(W_fc);

    // --- step 0 (SIMT fp32, K=768 input path) ---
    gru_step<<<dim3(NJB, BATCH / 64), 256>>>(src, OUTD, pWihf, b_ih,
                                             pH, pWhhf, b_hh,
                                             pH + (size_t)BATCH * HID);
    h2img<<<dim3(2, 16), 256>>>();

    // --- über-kernel ---
    uber<<<148, 256, UBER_DYN>>>(T, b_hh, out, b_fc);
}